// round 10
// baseline (speedup 1.0000x reference)
#include <cuda_runtime.h>
#include <cuda_bf16.h>
#include <cstdint>
#include <math.h>

// Problem constants
#define B_   4
#define S_   2048
#define C_   2048
#define NH   16
#define HD   128
#define QKV_LD 6144
#define MTOT (B_ * S_)          // 8192

// ---------------------------------------------------------------------------
// Scratch (__device__ globals — allocation-free rule)
// ---------------------------------------------------------------------------
__device__ __nv_bfloat16 g_qkvhi[(size_t)MTOT * QKV_LD];
__device__ __nv_bfloat16 g_qkvlo[(size_t)MTOT * QKV_LD];
__device__ __nv_bfloat16 g_xhi[(size_t)MTOT * C_];
__device__ __nv_bfloat16 g_xlo[(size_t)MTOT * C_];
__device__ __nv_bfloat16 g_yhi[(size_t)MTOT * C_];
__device__ __nv_bfloat16 g_ylo[(size_t)MTOT * C_];
__device__ __nv_bfloat16 g_wahi[(size_t)QKV_LD * C_];     // W_attn^T [6144,2048]
__device__ __nv_bfloat16 g_walo[(size_t)QKV_LD * C_];
__device__ __nv_bfloat16 g_wphi[(size_t)C_ * C_];         // W_proj^T [2048,2048]
__device__ __nv_bfloat16 g_wplo[(size_t)C_ * C_];

// ---------------------------------------------------------------------------
// PTX helpers (base compute_103 ISA: cp.async / ldmatrix / mma.sync)
// ---------------------------------------------------------------------------
__device__ __forceinline__ uint32_t smem_to_u32(const void* p) {
    uint32_t a;
    asm("{ .reg .u64 t; cvta.to.shared.u64 t, %1; cvt.u32.u64 %0, t; }" : "=r"(a) : "l"(p));
    return a;
}
__device__ __forceinline__ void cp16(uint32_t dst, const void* src) {
    asm volatile("cp.async.cg.shared.global [%0], [%1], 16;" :: "r"(dst), "l"(src));
}
#define CP_COMMIT() asm volatile("cp.async.commit_group;" ::: "memory")
#define CP_WAIT(n)  asm volatile("cp.async.wait_group %0;" :: "n"(n) : "memory")

__device__ __forceinline__ void ldsm_x4(uint32_t r[4], uint32_t addr) {
    asm volatile("ldmatrix.sync.aligned.m8n8.x4.shared.b16 {%0,%1,%2,%3}, [%4];"
        : "=r"(r[0]), "=r"(r[1]), "=r"(r[2]), "=r"(r[3]) : "r"(addr));
}
__device__ __forceinline__ void ldsm_x4_t(uint32_t r[4], uint32_t addr) {
    asm volatile("ldmatrix.sync.aligned.m8n8.x4.trans.shared.b16 {%0,%1,%2,%3}, [%4];"
        : "=r"(r[0]), "=r"(r[1]), "=r"(r[2]), "=r"(r[3]) : "r"(addr));
}
__device__ __forceinline__ void mma16816(float d[4], const uint32_t a[4], const uint32_t b[2]) {
    asm volatile(
        "mma.sync.aligned.m16n8k16.row.col.f32.bf16.bf16.f32 "
        "{%0,%1,%2,%3}, {%4,%5,%6,%7}, {%8,%9}, {%0,%1,%2,%3};"
        : "+f"(d[0]), "+f"(d[1]), "+f"(d[2]), "+f"(d[3])
        : "r"(a[0]), "r"(a[1]), "r"(a[2]), "r"(a[3]), "r"(b[0]), "r"(b[1]));
}
__device__ __forceinline__ float ex2f(float x) {
    float y; asm("ex2.approx.f32 %0, %1;" : "=f"(y) : "f"(x)); return y;
}
__device__ __forceinline__ uint32_t packhi2(float v0, float v1) {
    uint32_t r;
    asm("prmt.b32 %0, %1, %2, 0x7632;" : "=r"(r) : "r"(__float_as_uint(v0)), "r"(__float_as_uint(v1)));
    return r;
}
__device__ __forceinline__ float truncbf(float v) {
    return __uint_as_float(__float_as_uint(v) & 0xFFFF0000u);
}
__device__ __forceinline__ uint32_t packbf2(float lo, float hi) {
    uint32_t r;
    asm("cvt.rn.bf16x2.f32 %0, %1, %2;" : "=r"(r) : "f"(hi), "f"(lo));
    return r;
}

// ---------------------------------------------------------------------------
// Split fp32 -> (bf16 hi, bf16 lo)
// ---------------------------------------------------------------------------
__global__ void split_kernel(const float* __restrict__ in,
                             __nv_bfloat16* __restrict__ hi,
                             __nv_bfloat16* __restrict__ lo, int n4) {
    int i = blockIdx.x * blockDim.x + threadIdx.x;
    if (i >= n4) return;
    float4 v = ((const float4*)in)[i];
    float vv[4] = {v.x, v.y, v.z, v.w};
    __nv_bfloat16 h[4], l[4];
#pragma unroll
    for (int j = 0; j < 4; j++) {
        h[j] = __float2bfloat16(vv[j]);
        l[j] = __float2bfloat16(vv[j] - __bfloat162float(h[j]));
    }
    ((uint2*)hi)[i] = *(uint2*)h;
    ((uint2*)lo)[i] = *(uint2*)l;
}

// Transpose + split: in[K,N] fp32 -> hi/lo [N,K] bf16
__global__ void tsplit_kernel(const float* __restrict__ in,
                              __nv_bfloat16* __restrict__ hi,
                              __nv_bfloat16* __restrict__ lo, int K, int N) {
    __shared__ float t[32][33];
    int n0 = blockIdx.x * 32, k0 = blockIdx.y * 32;
    int tx = threadIdx.x, ty = threadIdx.y;
    for (int i = ty; i < 32; i += 8)
        t[i][tx] = in[(size_t)(k0 + i) * N + n0 + tx];
    __syncthreads();
    for (int i = ty; i < 32; i += 8) {
        float v = t[tx][i];
        __nv_bfloat16 h = __float2bfloat16(v);
        __nv_bfloat16 l = __float2bfloat16(v - __bfloat162float(h));
        size_t o = (size_t)(n0 + i) * K + k0 + tx;
        hi[o] = h;
        lo[o] = l;
    }
}

// ---------------------------------------------------------------------------
// HMMA split-precision GEMM: C[M,N] = A[M,K] @ B[N,K]^T
// CTA 128x128, BK=16, 6-stage swizzled smem, batch 3 kt per barrier,
// 256 threads = 8 warps as 4x2 (warp tile 32x64), 2 CTAs/SM.
// acc += Ahi*Bhi + Ahi*Blo + Alo*Bhi.
// Layout: 32B rows; 16B chunk c of row r at
//   (r>>2)*128 + (((c ^ ((r>>2)&1))*4 + (r&3)) * 16)   — conflict-free.
// ---------------------------------------------------------------------------
#define GT_T   4096                      // bytes per operand tile (128 x 32B)
#define GSTG   (4 * GT_T)                // 16384 (Ahi,Alo,Bhi,Blo)
#define GSTAGES 6
#define GEMM_SMEM (GSTAGES * GSTG)       // 98304

__device__ __forceinline__ uint32_t gaddr(int r, int c) {
    return (uint32_t)(((r >> 2) << 7) + ((((c ^ ((r >> 2) & 1)) << 2) + (r & 3)) << 4));
}

__global__ void __launch_bounds__(256, 2) gemm_hmma_kernel(
    const __nv_bfloat16* __restrict__ Ahi, const __nv_bfloat16* __restrict__ Alo,
    const __nv_bfloat16* __restrict__ Bhi, const __nv_bfloat16* __restrict__ Blo,
    float* __restrict__ C, __nv_bfloat16* __restrict__ Chi, __nv_bfloat16* __restrict__ Clo,
    int M, int N, int K)
{
    extern __shared__ char smem[];
    const uint32_t smb = smem_to_u32(smem);
    const int tid = threadIdx.x;
    const int wid = tid >> 5, lane = tid & 31;
    const int brow = blockIdx.y, bcol = blockIdx.x;
    const int NK = K >> 4;                       // BK=16 chunks (128)

    // fill one kt: each thread writes one 16B chunk per operand tile
    const int fr = tid >> 1, fc = tid & 1;
    const uint32_t foff = gaddr(fr, fc);
    auto fill = [&](int kt) {
        uint32_t sb = smb + (kt % GSTAGES) * GSTG;
        const int kof = kt * 16;
        size_t gA = (size_t)(brow * 128 + fr) * K + kof + fc * 8;
        size_t gB = (size_t)(bcol * 128 + fr) * K + kof + fc * 8;
        cp16(sb + foff, Ahi + gA);
        cp16(sb + GT_T + foff, Alo + gA);
        cp16(sb + 2 * GT_T + foff, Bhi + gB);
        cp16(sb + 3 * GT_T + foff, Blo + gB);
        CP_COMMIT();
    };

    float acc[2][8][4];
#pragma unroll
    for (int mf = 0; mf < 2; mf++)
#pragma unroll
        for (int nf = 0; nf < 8; nf++)
#pragma unroll
            for (int e = 0; e < 4; e++) acc[mf][nf][e] = 0.f;

    const int wm = wid & 3, wn = wid >> 2;       // 4 x 2 warp grid
    const int la = lane & 15, lah = lane >> 4;
    const int lbn2 = (lane & 7) + ((lane >> 4) << 3);
    const int lbkc = (lane >> 3) & 1;

    // precomputed per-lane ldsm offsets within an operand tile
    uint32_t offA[2], offB[4];
#pragma unroll
    for (int mf = 0; mf < 2; mf++) offA[mf] = gaddr(wm * 32 + la + mf * 16, lah);
#pragma unroll
    for (int np = 0; np < 4; np++) offB[np] = gaddr(wn * 64 + lbn2 + np * 16, lbkc);

    auto compute = [&](int kt) {
        uint32_t sb = smb + (kt % GSTAGES) * GSTG;
        uint32_t fah[2][4], fal[2][4];
#pragma unroll
        for (int mf = 0; mf < 2; mf++) {
            ldsm_x4(fah[mf], sb + offA[mf]);
            ldsm_x4(fal[mf], sb + GT_T + offA[mf]);
        }
#pragma unroll
        for (int np = 0; np < 4; np++) {
            uint32_t fbh[4], fbl[4];
            ldsm_x4(fbh, sb + 2 * GT_T + offB[np]);
            ldsm_x4(fbl, sb + 3 * GT_T + offB[np]);
#pragma unroll
            for (int mf = 0; mf < 2; mf++) {
                mma16816(acc[mf][2 * np],     fah[mf], fbh);
                mma16816(acc[mf][2 * np],     fah[mf], fbl);
                mma16816(acc[mf][2 * np],     fal[mf], fbh);
                mma16816(acc[mf][2 * np + 1], fah[mf], fbh + 2);
                mma16816(acc[mf][2 * np + 1], fah[mf], fbl + 2);
                mma16816(acc[mf][2 * np + 1], fal[mf], fbh + 2);
            }
        }
    };

    fill(0); fill(1); fill(2);
    for (int kp = 0; kp < NK; kp += 3) {
        CP_WAIT(0);                 // kt kp..kp+2 resident
        __syncthreads();            // prev batch fully consumed -> stages free
        if (kp + 3 < NK) fill(kp + 3);
        if (kp + 4 < NK) fill(kp + 4);
        if (kp + 5 < NK) fill(kp + 5);
        compute(kp);
        if (kp + 1 < NK) compute(kp + 1);
        if (kp + 2 < NK) compute(kp + 2);
    }

    // Epilogue
    const int r0 = brow * 128 + wm * 32 + (lane >> 2);
    const int c0 = bcol * 128 + wn * 64 + (lane & 3) * 2;
    if (C) {
#pragma unroll
        for (int mf = 0; mf < 2; mf++)
#pragma unroll
            for (int nf = 0; nf < 8; nf++) {
                int row = r0 + mf * 16, col = c0 + nf * 8;
                *(float2*)&C[(size_t)row * N + col] = make_float2(acc[mf][nf][0], acc[mf][nf][1]);
                *(float2*)&C[(size_t)(row + 8) * N + col] = make_float2(acc[mf][nf][2], acc[mf][nf][3]);
            }
    } else {
#pragma unroll
        for (int mf = 0; mf < 2; mf++)
#pragma unroll
            for (int nf = 0; nf < 8; nf++) {
                int row = r0 + mf * 16, col = c0 + nf * 8;
                float* a = acc[mf][nf];
                float h0 = truncbf(a[0]), h1 = truncbf(a[1]), h2 = truncbf(a[2]), h3 = truncbf(a[3]);
                *(uint32_t*)&Chi[(size_t)row * N + col] = packhi2(a[0], a[1]);
                *(uint32_t*)&Chi[(size_t)(row + 8) * N + col] = packhi2(a[2], a[3]);
                *(uint32_t*)&Clo[(size_t)row * N + col] = packbf2(a[0] - h0, a[1] - h1);
                *(uint32_t*)&Clo[(size_t)(row + 8) * N + col] = packbf2(a[2] - h2, a[3] - h3);
            }
    }
}

// ---------------------------------------------------------------------------
// Causal flash attention on tensor cores (bf16 hi/lo split precision).
// CTA = 128 q rows of one (b,h); 8 warps, each warp 16 full rows.
// Q fragments held in registers (loaded once); 3-stage KV pipeline with a
// single __syncthreads per kv-block.
// ---------------------------------------------------------------------------
#define AROWB 272                        // 128 bf16 = 256B + 16B pad
#define KHI_O 0
#define KLO_O (64 * AROWB)               // 17408
#define VHI_O (2 * 64 * AROWB)
#define VLO_O (3 * 64 * AROWB)
#define STG_SZ (4 * 64 * AROWB)          // 69632
#define ATTN_SMEM (3 * STG_SZ)           // 208896

__global__ void __launch_bounds__(256, 1) attn_mma_kernel(
    const __nv_bfloat16* __restrict__ qhv, const __nv_bfloat16* __restrict__ qlv,
    __nv_bfloat16* __restrict__ yhi, __nv_bfloat16* __restrict__ ylo)
{
    extern __shared__ char smem[];
    const uint32_t smb = smem_to_u32(smem);
    const int tid = threadIdx.x, wid = tid >> 5, lane = tid & 31;
    const int qb = 15 - blockIdx.x;              // heavy CTAs first
    const int bh = blockIdx.y, b = bh >> 4, h = bh & 15;
    const int nkb = 2 * qb + 2;
    const size_t gbase = (size_t)b * S_ * QKV_LD + (size_t)h * HD;
    const float csc = 0.12752963413397017f;      // 1/sqrt(128) * log2(e)

    // ---- Prologue: stage Q in stage-2's smem, ldsm into registers ----
    const uint32_t qsb = smb + 2 * STG_SZ;       // Q hi rows 0-127, lo at +128*AROWB
#pragma unroll
    for (int t = 0; t < 8; t++) {
        int idx = tid + t * 256;                 // 0..2047
        int r = idx >> 4, c = idx & 15;
        size_t g = gbase + (size_t)(qb * 128 + r) * QKV_LD + c * 8;
        cp16(qsb + r * AROWB + c * 16, qhv + g);
        cp16(qsb + 128 * AROWB + r * AROWB + c * 16, qlv + g);
    }
    CP_COMMIT();

    const int la = lane & 15, lah = lane >> 4;
    const int lbn2 = (lane & 7) + ((lane >> 4) << 3);
    const int lbk2 = ((lane >> 3) & 1) * 16;
    const int grow = qb * 128 + wid * 16 + (lane >> 2);

    CP_WAIT(0);
    __syncthreads();
    uint32_t Qh[8][4], Ql[8][4];
    {
        const uint32_t aQ = qsb + (wid * 16 + la) * AROWB + lah * 16;
#pragma unroll
        for (int ks = 0; ks < 8; ks++) {
            ldsm_x4(Qh[ks], aQ + ks * 32);
            ldsm_x4(Ql[ks], aQ + 128 * AROWB + ks * 32);
        }
    }
    __syncthreads();   // everyone done reading Q smem before stage 2 is recycled

    auto fillKV = [&](int kb) {
        uint32_t sb = smb + (kb % 3) * STG_SZ;
#pragma unroll
        for (int t = 0; t < 4; t++) {
            int idx = tid + t * 256;             // 0..1023
            int r = idx >> 4, c = idx & 15;
            size_t g = gbase + (size_t)(kb * 64 + r) * QKV_LD + c * 8;
            cp16(sb + KHI_O + r * AROWB + c * 16, qhv + g + C_);
            cp16(sb + KLO_O + r * AROWB + c * 16, qlv + g + C_);
            cp16(sb + VHI_O + r * AROWB + c * 16, qhv + g + 2 * C_);
            cp16(sb + VLO_O + r * AROWB + c * 16, qlv + g + 2 * C_);
        }
        CP_COMMIT();
    };
    fillKV(0);
    fillKV(1);

    float O[16][4];
#pragma unroll
    for (int nf = 0; nf < 16; nf++)
#pragma unroll
        for (int e = 0; e < 4; e++) O[nf][e] = 0.f;
    float m0 = -1e30f, m1 = -1e30f, l0 = 0.f, l1 = 0.f;

    for (int kb = 0; kb < nkb; kb++) {
        CP_WAIT(1);
        __syncthreads();             // stage kb visible; stage kb+2 (==kb-1) free
        if (kb + 2 < nkb) fillKV(kb + 2);
        const uint32_t kvb = smb + (kb % 3) * STG_SZ;
        const uint32_t aKh = kvb + KHI_O + lbn2 * AROWB + lbk2;
        const uint32_t aKl = kvb + KLO_O + lbn2 * AROWB + lbk2;

        // ---- S = Q K^T (scaled to base-2 domain) ----
        float S[8][4];
#pragma unroll
        for (int nf = 0; nf < 8; nf++)
#pragma unroll
            for (int e = 0; e < 4; e++) S[nf][e] = 0.f;

#pragma unroll
        for (int ks = 0; ks < 8; ks++) {
#pragma unroll
            for (int np = 0; np < 4; np++) {
                uint32_t fkh[4], fkl[4];
                ldsm_x4(fkh, aKh + np * 16 * AROWB + ks * 32);
                ldsm_x4(fkl, aKl + np * 16 * AROWB + ks * 32);
                mma16816(S[2 * np],     Qh[ks], fkh);
                mma16816(S[2 * np],     Qh[ks], fkl);
                mma16816(S[2 * np],     Ql[ks], fkh);
                mma16816(S[2 * np + 1], Qh[ks], fkh + 2);
                mma16816(S[2 * np + 1], Qh[ks], fkl + 2);
                mma16816(S[2 * np + 1], Ql[ks], fkh + 2);
            }
        }

        // ---- scale + causal mask ----
        const bool diag = (kb >= 2 * qb);
#pragma unroll
        for (int nf = 0; nf < 8; nf++)
#pragma unroll
            for (int e = 0; e < 4; e++) {
                float v = S[nf][e] * csc;
                if (diag) {
                    int col = kb * 64 + nf * 8 + (lane & 3) * 2 + (e & 1);
                    int row = grow + ((e & 2) ? 8 : 0);
                    if (col > row) v = -1e30f;
                }
                S[nf][e] = v;
            }

        // ---- online softmax ----
        float t0 = -1e30f, t1 = -1e30f;
#pragma unroll
        for (int nf = 0; nf < 8; nf++) {
            t0 = fmaxf(t0, fmaxf(S[nf][0], S[nf][1]));
            t1 = fmaxf(t1, fmaxf(S[nf][2], S[nf][3]));
        }
        t0 = fmaxf(t0, __shfl_xor_sync(0xffffffffu, t0, 1));
        t0 = fmaxf(t0, __shfl_xor_sync(0xffffffffu, t0, 2));
        t1 = fmaxf(t1, __shfl_xor_sync(0xffffffffu, t1, 1));
        t1 = fmaxf(t1, __shfl_xor_sync(0xffffffffu, t1, 2));
        float mn0 = fmaxf(m0, t0), mn1 = fmaxf(m1, t1);
        float a0 = ex2f(m0 - mn0), a1 = ex2f(m1 - mn1);
        m0 = mn0; m1 = mn1;
        float rs0 = 0.f, rs1 = 0.f;
#pragma unroll
        for (int nf = 0; nf < 8; nf++) {
            S[nf][0] = ex2f(S[nf][0] - mn0);
            S[nf][1] = ex2f(S[nf][1] - mn0);
            S[nf][2] = ex2f(S[nf][2] - mn1);
            S[nf][3] = ex2f(S[nf][3] - mn1);
            rs0 += S[nf][0] + S[nf][1];
            rs1 += S[nf][2] + S[nf][3];
        }
        l0 = l0 * a0 + rs0;
        l1 = l1 * a1 + rs1;
#pragma unroll
        for (int nf = 0; nf < 16; nf++) {
            O[nf][0] *= a0; O[nf][1] *= a0; O[nf][2] *= a1; O[nf][3] *= a1;
        }

        // ---- O += P V (P split hi/lo in registers) ----
#pragma unroll
        for (int kk = 0; kk < 4; kk++) {
            float* s0 = S[2 * kk];
            float* s1 = S[2 * kk + 1];
            uint32_t ph[4], pl[4];
            ph[0] = packhi2(s0[0], s0[1]);
            ph[1] = packhi2(s0[2], s0[3]);
            ph[2] = packhi2(s1[0], s1[1]);
            ph[3] = packhi2(s1[2], s1[3]);
            pl[0] = packbf2(s0[0] - truncbf(s0[0]), s0[1] - truncbf(s0[1]));
            pl[1] = packbf2(s0[2] - truncbf(s0[2]), s0[3] - truncbf(s0[3]));
            pl[2] = packbf2(s1[0] - truncbf(s1[0]), s1[1] - truncbf(s1[1]));
            pl[3] = packbf2(s1[2] - truncbf(s1[2]), s1[3] - truncbf(s1[3]));
#pragma unroll
            for (int n2 = 0; n2 < 8; n2++) {
                uint32_t fvh[4], fvl[4];
                ldsm_x4_t(fvh, kvb + VHI_O + (kk * 16 + la) * AROWB + n2 * 32 + lah * 16);
                ldsm_x4_t(fvl, kvb + VLO_O + (kk * 16 + la) * AROWB + n2 * 32 + lah * 16);
                mma16816(O[2 * n2],     ph, fvh);
                mma16816(O[2 * n2],     ph, fvl);
                mma16816(O[2 * n2],     pl, fvh);
                mma16816(O[2 * n2 + 1], ph, fvh + 2);
                mma16816(O[2 * n2 + 1], ph, fvl + 2);
                mma16816(O[2 * n2 + 1], pl, fvh + 2);
            }
        }
    }

    // ---- epilogue: O/l, split to bf16 hi/lo ----
    l0 += __shfl_xor_sync(0xffffffffu, l0, 1);
    l0 += __shfl_xor_sync(0xffffffffu, l0, 2);
    l1 += __shfl_xor_sync(0xffffffffu, l1, 1);
    l1 += __shfl_xor_sync(0xffffffffu, l1, 2);
    const float i0 = 1.f / l0, i1 = 1.f / l1;
    const size_t o0 = ((size_t)b * S_ + grow) * C_ + h * HD + (lane & 3) * 2;
    const size_t o1 = o0 + 8 * C_;
#pragma unroll
    for (int nf = 0; nf < 16; nf++) {
        float v0 = O[nf][0] * i0, v1 = O[nf][1] * i0;
        float v2 = O[nf][2] * i1, v3 = O[nf][3] * i1;
        *(uint32_t*)(yhi + o0 + nf * 8) = packhi2(v0, v1);
        *(uint32_t*)(ylo + o0 + nf * 8) = packbf2(v0 - truncbf(v0), v1 - truncbf(v1));
        *(uint32_t*)(yhi + o1 + nf * 8) = packhi2(v2, v3);
        *(uint32_t*)(ylo + o1 + nf * 8) = packbf2(v2 - truncbf(v2), v3 - truncbf(v3));
    }
}

// ---------------------------------------------------------------------------
extern "C" void kernel_launch(void* const* d_in, const int* in_sizes, int n_in,
                              void* d_out, int out_size) {
    const float* x  = (const float*)d_in[0];
    const float* Wa = (const float*)d_in[1];
    const float* Wp = (const float*)d_in[2];
    float* out = (float*)d_out;

    __nv_bfloat16 *qkvhi, *qkvlo, *xhi, *xlo, *yhi, *ylo, *wahi, *walo, *wphi, *wplo;
    cudaGetSymbolAddress((void**)&qkvhi, g_qkvhi);
    cudaGetSymbolAddress((void**)&qkvlo, g_qkvlo);
    cudaGetSymbolAddress((void**)&xhi, g_xhi);
    cudaGetSymbolAddress((void**)&xlo, g_xlo);
    cudaGetSymbolAddress((void**)&yhi, g_yhi);
    cudaGetSymbolAddress((void**)&ylo, g_ylo);
    cudaGetSymbolAddress((void**)&wahi, g_wahi);
    cudaGetSymbolAddress((void**)&walo, g_walo);
    cudaGetSymbolAddress((void**)&wphi, g_wphi);
    cudaGetSymbolAddress((void**)&wplo, g_wplo);

    cudaFuncSetAttribute(gemm_hmma_kernel, cudaFuncAttributeMaxDynamicSharedMemorySize, GEMM_SMEM);
    cudaFuncSetAttribute(attn_mma_kernel, cudaFuncAttributeMaxDynamicSharedMemorySize, ATTN_SMEM);

    // 0) split/transpose operands
    int n4 = (MTOT * C_) / 4;
    split_kernel<<<(n4 + 255) / 256, 256>>>(x, xhi, xlo, n4);
    dim3 bT(32, 8);
    tsplit_kernel<<<dim3(QKV_LD / 32, C_ / 32), bT>>>(Wa, wahi, walo, C_, QKV_LD);
    tsplit_kernel<<<dim3(C_ / 32, C_ / 32), bT>>>(Wp, wphi, wplo, C_, C_);

    // 1) QKV projection -> bf16 hi/lo directly
    gemm_hmma_kernel<<<dim3(QKV_LD / 128, MTOT / 128), 256, GEMM_SMEM>>>(
        xhi, xlo, wahi, walo, nullptr, qkvhi, qkvlo, MTOT, QKV_LD, C_);

    // 2) Causal flash attention (tensor cores) -> y hi/lo
    attn_mma_kernel<<<dim3(16, B_ * NH), 256, ATTN_SMEM>>>(qkvhi, qkvlo, yhi, ylo);

    // 3) Output projection -> fp32 out
    gemm_hmma_kernel<<<dim3(C_ / 128, MTOT / 128), 256, GEMM_SMEM>>>(
        yhi, ylo, wphi, wplo, out, nullptr, nullptr, MTOT, C_, C_);
}

// round 11
// speedup vs baseline: 1.3383x; 1.3383x over previous
#include <cuda_runtime.h>
#include <cuda_bf16.h>
#include <cstdint>
#include <math.h>

// Problem constants
#define B_   4
#define S_   2048
#define C_   2048
#define NH   16
#define HD   128
#define QKV_LD 6144
#define MTOT (B_ * S_)          // 8192

// ---------------------------------------------------------------------------
// Scratch (__device__ globals — allocation-free rule)
// ---------------------------------------------------------------------------
__device__ __nv_bfloat16 g_qkvhi[(size_t)MTOT * QKV_LD];
__device__ __nv_bfloat16 g_qkvlo[(size_t)MTOT * QKV_LD];
__device__ __nv_bfloat16 g_xhi[(size_t)MTOT * C_];
__device__ __nv_bfloat16 g_xlo[(size_t)MTOT * C_];
__device__ __nv_bfloat16 g_yhi[(size_t)MTOT * C_];
__device__ __nv_bfloat16 g_ylo[(size_t)MTOT * C_];
__device__ __nv_bfloat16 g_wahi[(size_t)QKV_LD * C_];     // W_attn^T [6144,2048]
__device__ __nv_bfloat16 g_walo[(size_t)QKV_LD * C_];
__device__ __nv_bfloat16 g_wphi[(size_t)C_ * C_];         // W_proj^T [2048,2048]
__device__ __nv_bfloat16 g_wplo[(size_t)C_ * C_];

// ---------------------------------------------------------------------------
// PTX helpers (base compute_103 ISA: cp.async / ldmatrix / mma.sync)
// ---------------------------------------------------------------------------
__device__ __forceinline__ uint32_t smem_to_u32(const void* p) {
    uint32_t a;
    asm("{ .reg .u64 t; cvta.to.shared.u64 t, %1; cvt.u32.u64 %0, t; }" : "=r"(a) : "l"(p));
    return a;
}
__device__ __forceinline__ void cp16(uint32_t dst, const void* src) {
    asm volatile("cp.async.cg.shared.global [%0], [%1], 16;" :: "r"(dst), "l"(src));
}
#define CP_COMMIT() asm volatile("cp.async.commit_group;" ::: "memory")
#define CP_WAIT(n)  asm volatile("cp.async.wait_group %0;" :: "n"(n) : "memory")

__device__ __forceinline__ void ldsm_x4(uint32_t r[4], uint32_t addr) {
    asm volatile("ldmatrix.sync.aligned.m8n8.x4.shared.b16 {%0,%1,%2,%3}, [%4];"
        : "=r"(r[0]), "=r"(r[1]), "=r"(r[2]), "=r"(r[3]) : "r"(addr));
}
__device__ __forceinline__ void ldsm_x4_t(uint32_t r[4], uint32_t addr) {
    asm volatile("ldmatrix.sync.aligned.m8n8.x4.trans.shared.b16 {%0,%1,%2,%3}, [%4];"
        : "=r"(r[0]), "=r"(r[1]), "=r"(r[2]), "=r"(r[3]) : "r"(addr));
}
__device__ __forceinline__ void mma16816(float d[4], const uint32_t a[4], const uint32_t b[2]) {
    asm volatile(
        "mma.sync.aligned.m16n8k16.row.col.f32.bf16.bf16.f32 "
        "{%0,%1,%2,%3}, {%4,%5,%6,%7}, {%8,%9}, {%0,%1,%2,%3};"
        : "+f"(d[0]), "+f"(d[1]), "+f"(d[2]), "+f"(d[3])
        : "r"(a[0]), "r"(a[1]), "r"(a[2]), "r"(a[3]), "r"(b[0]), "r"(b[1]));
}
__device__ __forceinline__ float ex2f(float x) {
    float y; asm("ex2.approx.f32 %0, %1;" : "=f"(y) : "f"(x)); return y;
}
__device__ __forceinline__ uint32_t packhi2(float v0, float v1) {
    uint32_t r;
    asm("prmt.b32 %0, %1, %2, 0x7632;" : "=r"(r) : "r"(__float_as_uint(v0)), "r"(__float_as_uint(v1)));
    return r;
}
__device__ __forceinline__ float truncbf(float v) {
    return __uint_as_float(__float_as_uint(v) & 0xFFFF0000u);
}
__device__ __forceinline__ uint32_t packbf2(float lo, float hi) {
    uint32_t r;
    asm("cvt.rn.bf16x2.f32 %0, %1, %2;" : "=r"(r) : "f"(hi), "f"(lo));
    return r;
}

// ---------------------------------------------------------------------------
// Split fp32 -> (bf16 hi, bf16 lo)
// ---------------------------------------------------------------------------
__global__ void split_kernel(const float* __restrict__ in,
                             __nv_bfloat16* __restrict__ hi,
                             __nv_bfloat16* __restrict__ lo, int n4) {
    int i = blockIdx.x * blockDim.x + threadIdx.x;
    if (i >= n4) return;
    float4 v = ((const float4*)in)[i];
    float vv[4] = {v.x, v.y, v.z, v.w};
    __nv_bfloat16 h[4], l[4];
#pragma unroll
    for (int j = 0; j < 4; j++) {
        h[j] = __float2bfloat16(vv[j]);
        l[j] = __float2bfloat16(vv[j] - __bfloat162float(h[j]));
    }
    ((uint2*)hi)[i] = *(uint2*)h;
    ((uint2*)lo)[i] = *(uint2*)l;
}

// Transpose + split: in[K,N] fp32 -> hi/lo [N,K] bf16
__global__ void tsplit_kernel(const float* __restrict__ in,
                              __nv_bfloat16* __restrict__ hi,
                              __nv_bfloat16* __restrict__ lo, int K, int N) {
    __shared__ float t[32][33];
    int n0 = blockIdx.x * 32, k0 = blockIdx.y * 32;
    int tx = threadIdx.x, ty = threadIdx.y;
    for (int i = ty; i < 32; i += 8)
        t[i][tx] = in[(size_t)(k0 + i) * N + n0 + tx];
    __syncthreads();
    for (int i = ty; i < 32; i += 8) {
        float v = t[tx][i];
        __nv_bfloat16 h = __float2bfloat16(v);
        __nv_bfloat16 l = __float2bfloat16(v - __bfloat162float(h));
        size_t o = (size_t)(n0 + i) * K + k0 + tx;
        hi[o] = h;
        lo[o] = l;
    }
}

// ---------------------------------------------------------------------------
// HMMA split-precision GEMM: C[M,N] = A[M,K] @ B[N,K]^T
// CTA 128x128, BK=32, 3-stage XOR-swizzled smem, 256 threads = 8 warps as
// 4x2 (warp tile 32x64), 2 CTAs/SM so barriers only stall half the SM.
// A-fragment ldsm hoisted before the fill to shorten the post-barrier ramp.
// acc += Ahi*Bhi + Ahi*Blo + Alo*Bhi.
// Swizzle: 16B chunk c of row r stored at r*64 + ((c ^ ((r>>1)&3))*16).
// ---------------------------------------------------------------------------
#define GA_T   (128 * 64)                // 8192
#define GB_T   (128 * 64)                // 8192
#define GSTG   (2 * GA_T + 2 * GB_T)     // 32768
#define GEMM_SMEM (3 * GSTG)             // 98304

__global__ void __launch_bounds__(256, 2) gemm_hmma_kernel(
    const __nv_bfloat16* __restrict__ Ahi, const __nv_bfloat16* __restrict__ Alo,
    const __nv_bfloat16* __restrict__ Bhi, const __nv_bfloat16* __restrict__ Blo,
    float* __restrict__ C, __nv_bfloat16* __restrict__ Chi, __nv_bfloat16* __restrict__ Clo,
    int M, int N, int K)
{
    extern __shared__ char smem[];
    const uint32_t smb = smem_to_u32(smem);
    const int tid = threadIdx.x;
    const int wid = tid >> 5, lane = tid & 31;
    const int brow = blockIdx.y, bcol = blockIdx.x;
    const int NK = K >> 5;

    // fill: swizzled stores. 512 16B-chunks per operand tile, 2 per thread.
    auto fill = [&](int st, int kt) {
        uint32_t sb = smb + st * GSTG;
        const int kof = kt * 32;
#pragma unroll
        for (int t = 0; t < 2; t++) {
            int idx = tid + t * 256;
            int r = idx >> 2, c = idx & 3;
            uint32_t off = r * 64 + ((c ^ ((r >> 1) & 3)) << 4);
            size_t gA = (size_t)(brow * 128 + r) * K + kof + c * 8;
            size_t gB = (size_t)(bcol * 128 + r) * K + kof + c * 8;
            cp16(sb + off, Ahi + gA);
            cp16(sb + GA_T + off, Alo + gA);
            cp16(sb + 2 * GA_T + off, Bhi + gB);
            cp16(sb + 2 * GA_T + GB_T + off, Blo + gB);
        }
        CP_COMMIT();
    };

    float acc[2][8][4];
#pragma unroll
    for (int mf = 0; mf < 2; mf++)
#pragma unroll
        for (int nf = 0; nf < 8; nf++)
#pragma unroll
            for (int e = 0; e < 4; e++) acc[mf][nf][e] = 0.f;

    const int wm = wid & 3, wn = wid >> 2;       // 4 x 2 warp grid
    const int la = lane & 15, lah = lane >> 4;
    const int lbn2 = (lane & 7) + ((lane >> 4) << 3);
    const int lbkc = (lane >> 3) & 1;

    const int rowA = wm * 32 + la;
    const int keyA = (rowA >> 1) & 3;
    const int rowB = wn * 64 + lbn2;
    const int keyB = (rowB >> 1) & 3;

    fill(0, 0);
    fill(1, 1);

    for (int kt = 0; kt < NK; kt++) {
        CP_WAIT(1);                 // stage kt resident (kt+1 may be in flight)
        __syncthreads();

        uint32_t sb = smb + (kt % 3) * GSTG;
        uint32_t baseA = sb + rowA * 64;
        uint32_t baseB = sb + 2 * GA_T + rowB * 64;

        // Hoist ALL A fragments (both ks halves) before the fill: their
        // latency hides under the fill's cp.async issue, and ks=1 runs with
        // no A loads in its shadow.
        uint32_t fah[2][2][4], fal[2][2][4];     // [ks][mf]
#pragma unroll
        for (int ks = 0; ks < 2; ks++) {
            const uint32_t cAo = (uint32_t)(((ks * 2 + lah) ^ keyA) << 4);
#pragma unroll
            for (int mf = 0; mf < 2; mf++) {
                ldsm_x4(fah[ks][mf], baseA + mf * 1024 + cAo);
                ldsm_x4(fal[ks][mf], baseA + GA_T + mf * 1024 + cAo);
            }
        }

        if (kt + 2 < NK) fill((kt + 2) % 3, kt + 2);
        else CP_COMMIT();

#pragma unroll
        for (int ks = 0; ks < 2; ks++) {
            const uint32_t cBo = (uint32_t)(((ks * 2 + lbkc) ^ keyB) << 4);
#pragma unroll
            for (int np = 0; np < 4; np++) {
                uint32_t fbh[4], fbl[4];
                ldsm_x4(fbh, baseB + np * 1024 + cBo);
                ldsm_x4(fbl, baseB + GB_T + np * 1024 + cBo);
#pragma unroll
                for (int mf = 0; mf < 2; mf++) {
                    mma16816(acc[mf][2 * np],     fah[ks][mf], fbh);
                    mma16816(acc[mf][2 * np],     fah[ks][mf], fbl);
                    mma16816(acc[mf][2 * np],     fal[ks][mf], fbh);
                    mma16816(acc[mf][2 * np + 1], fah[ks][mf], fbh + 2);
                    mma16816(acc[mf][2 * np + 1], fah[ks][mf], fbl + 2);
                    mma16816(acc[mf][2 * np + 1], fal[ks][mf], fbh + 2);
                }
            }
        }
    }

    // Epilogue
    const int r0 = brow * 128 + wm * 32 + (lane >> 2);
    const int c0 = bcol * 128 + wn * 64 + (lane & 3) * 2;
    if (C) {
#pragma unroll
        for (int mf = 0; mf < 2; mf++)
#pragma unroll
            for (int nf = 0; nf < 8; nf++) {
                int row = r0 + mf * 16, col = c0 + nf * 8;
                *(float2*)&C[(size_t)row * N + col] = make_float2(acc[mf][nf][0], acc[mf][nf][1]);
                *(float2*)&C[(size_t)(row + 8) * N + col] = make_float2(acc[mf][nf][2], acc[mf][nf][3]);
            }
    } else {
#pragma unroll
        for (int mf = 0; mf < 2; mf++)
#pragma unroll
            for (int nf = 0; nf < 8; nf++) {
                int row = r0 + mf * 16, col = c0 + nf * 8;
                float* a = acc[mf][nf];
                float h0 = truncbf(a[0]), h1 = truncbf(a[1]), h2 = truncbf(a[2]), h3 = truncbf(a[3]);
                *(uint32_t*)&Chi[(size_t)row * N + col] = packhi2(a[0], a[1]);
                *(uint32_t*)&Chi[(size_t)(row + 8) * N + col] = packhi2(a[2], a[3]);
                *(uint32_t*)&Clo[(size_t)row * N + col] = packbf2(a[0] - h0, a[1] - h1);
                *(uint32_t*)&Clo[(size_t)(row + 8) * N + col] = packbf2(a[2] - h2, a[3] - h3);
            }
    }
}

// ---------------------------------------------------------------------------
// Causal flash attention on tensor cores (bf16 hi/lo split precision).
// CTA = 128 q rows of one (b,h); 8 warps, each warp 16 full rows.
// K/V double-buffered (64-row blocks). Exact R9 version (best measured).
// ---------------------------------------------------------------------------
#define AROWB 272                        // 128 bf16 = 256B + 16B pad
#define SQ_HI 0
#define SQ_LO (128 * AROWB)              // 34816
#define SKV   (2 * 128 * AROWB)          // 69632
#define KHI_O 0
#define KLO_O (64 * AROWB)               // 17408
#define VHI_O (2 * 64 * AROWB)
#define VLO_O (3 * 64 * AROWB)
#define STG_SZ (4 * 64 * AROWB)          // 69632
#define ATTN_SMEM (SKV + 2 * STG_SZ)     // 208896

__global__ void __launch_bounds__(256, 1) attn_mma_kernel(
    const __nv_bfloat16* __restrict__ qhv, const __nv_bfloat16* __restrict__ qlv,
    __nv_bfloat16* __restrict__ yhi, __nv_bfloat16* __restrict__ ylo)
{
    extern __shared__ char smem[];
    const uint32_t smb = smem_to_u32(smem);
    const int tid = threadIdx.x, wid = tid >> 5, lane = tid & 31;
    const int qb = 15 - blockIdx.x;              // heavy CTAs first
    const int bh = blockIdx.y, b = bh >> 4, h = bh & 15;
    const int nkb = 2 * qb + 2;
    const size_t gbase = (size_t)b * S_ * QKV_LD + (size_t)h * HD;
    const float csc = 0.12752963413397017f;      // 1/sqrt(128) * log2(e)

    // Q tile (hi+lo), 128 rows
#pragma unroll
    for (int t = 0; t < 8; t++) {
        int idx = tid + t * 256;                 // 0..2047
        int r = idx >> 4, c = idx & 15;
        size_t g = gbase + (size_t)(qb * 128 + r) * QKV_LD + c * 8;
        cp16(smb + SQ_HI + r * AROWB + c * 16, qhv + g);
        cp16(smb + SQ_LO + r * AROWB + c * 16, qlv + g);
    }
    auto fillKV = [&](int st, int kb) {
        uint32_t sb = smb + SKV + st * STG_SZ;
#pragma unroll
        for (int t = 0; t < 4; t++) {
            int idx = tid + t * 256;             // 0..1023
            int r = idx >> 4, c = idx & 15;
            size_t g = gbase + (size_t)(kb * 64 + r) * QKV_LD + c * 8;
            cp16(sb + KHI_O + r * AROWB + c * 16, qhv + g + C_);
            cp16(sb + KLO_O + r * AROWB + c * 16, qlv + g + C_);
            cp16(sb + VHI_O + r * AROWB + c * 16, qhv + g + 2 * C_);
            cp16(sb + VLO_O + r * AROWB + c * 16, qlv + g + 2 * C_);
        }
        CP_COMMIT();
    };
    fillKV(0, 0);    // Q cp.asyncs are folded into this first group
    fillKV(1, 1);

    float O[16][4];
#pragma unroll
    for (int nf = 0; nf < 16; nf++)
#pragma unroll
        for (int e = 0; e < 4; e++) O[nf][e] = 0.f;
    float m0 = -1e30f, m1 = -1e30f, l0 = 0.f, l1 = 0.f;

    const int la = lane & 15, lah = lane >> 4;
    const int lbn2 = (lane & 7) + ((lane >> 4) << 3);
    const int lbk2 = ((lane >> 3) & 1) * 16;
    const uint32_t aQh = smb + SQ_HI + (wid * 16 + la) * AROWB + lah * 16;
    const uint32_t aQl = aQh + (SQ_LO - SQ_HI);
    const int grow = qb * 128 + wid * 16 + (lane >> 2);

    for (int kb = 0; kb < nkb; kb++) {
        const int cur = kb & 1;
        CP_WAIT(1);
        __syncthreads();
        const uint32_t kvb = smb + SKV + cur * STG_SZ;
        const uint32_t aKh = kvb + KHI_O + lbn2 * AROWB + lbk2;
        const uint32_t aKl = kvb + KLO_O + lbn2 * AROWB + lbk2;

        // ---- S = Q K^T (scaled to base-2 domain) ----
        float S[8][4];
#pragma unroll
        for (int nf = 0; nf < 8; nf++)
#pragma unroll
            for (int e = 0; e < 4; e++) S[nf][e] = 0.f;

#pragma unroll
        for (int ks = 0; ks < 8; ks++) {
            uint32_t fqh[4], fql[4];
            ldsm_x4(fqh, aQh + ks * 32);
            ldsm_x4(fql, aQl + ks * 32);
#pragma unroll
            for (int np = 0; np < 4; np++) {
                uint32_t fkh[4], fkl[4];
                ldsm_x4(fkh, aKh + np * 16 * AROWB + ks * 32);
                ldsm_x4(fkl, aKl + np * 16 * AROWB + ks * 32);
                mma16816(S[2 * np],     fqh, fkh);
                mma16816(S[2 * np],     fqh, fkl);
                mma16816(S[2 * np],     fql, fkh);
                mma16816(S[2 * np + 1], fqh, fkh + 2);
                mma16816(S[2 * np + 1], fqh, fkl + 2);
                mma16816(S[2 * np + 1], fql, fkh + 2);
            }
        }

        // ---- scale + causal mask ----
        const bool diag = (kb >= 2 * qb);
#pragma unroll
        for (int nf = 0; nf < 8; nf++)
#pragma unroll
            for (int e = 0; e < 4; e++) {
                float v = S[nf][e] * csc;
                if (diag) {
                    int col = kb * 64 + nf * 8 + (lane & 3) * 2 + (e & 1);
                    int row = grow + ((e & 2) ? 8 : 0);
                    if (col > row) v = -1e30f;
                }
                S[nf][e] = v;
            }

        // ---- online softmax ----
        float t0 = -1e30f, t1 = -1e30f;
#pragma unroll
        for (int nf = 0; nf < 8; nf++) {
            t0 = fmaxf(t0, fmaxf(S[nf][0], S[nf][1]));
            t1 = fmaxf(t1, fmaxf(S[nf][2], S[nf][3]));
        }
        t0 = fmaxf(t0, __shfl_xor_sync(0xffffffffu, t0, 1));
        t0 = fmaxf(t0, __shfl_xor_sync(0xffffffffu, t0, 2));
        t1 = fmaxf(t1, __shfl_xor_sync(0xffffffffu, t1, 1));
        t1 = fmaxf(t1, __shfl_xor_sync(0xffffffffu, t1, 2));
        float mn0 = fmaxf(m0, t0), mn1 = fmaxf(m1, t1);
        float a0 = ex2f(m0 - mn0), a1 = ex2f(m1 - mn1);
        m0 = mn0; m1 = mn1;
        float rs0 = 0.f, rs1 = 0.f;
#pragma unroll
        for (int nf = 0; nf < 8; nf++) {
            S[nf][0] = ex2f(S[nf][0] - mn0);
            S[nf][1] = ex2f(S[nf][1] - mn0);
            S[nf][2] = ex2f(S[nf][2] - mn1);
            S[nf][3] = ex2f(S[nf][3] - mn1);
            rs0 += S[nf][0] + S[nf][1];
            rs1 += S[nf][2] + S[nf][3];
        }
        l0 = l0 * a0 + rs0;
        l1 = l1 * a1 + rs1;
#pragma unroll
        for (int nf = 0; nf < 16; nf++) {
            O[nf][0] *= a0; O[nf][1] *= a0; O[nf][2] *= a1; O[nf][3] *= a1;
        }

        // ---- O += P V (P split hi/lo in registers) ----
#pragma unroll
        for (int kk = 0; kk < 4; kk++) {
            float* s0 = S[2 * kk];
            float* s1 = S[2 * kk + 1];
            uint32_t ph[4], pl[4];
            ph[0] = packhi2(s0[0], s0[1]);
            ph[1] = packhi2(s0[2], s0[3]);
            ph[2] = packhi2(s1[0], s1[1]);
            ph[3] = packhi2(s1[2], s1[3]);
            pl[0] = packbf2(s0[0] - truncbf(s0[0]), s0[1] - truncbf(s0[1]));
            pl[1] = packbf2(s0[2] - truncbf(s0[2]), s0[3] - truncbf(s0[3]));
            pl[2] = packbf2(s1[0] - truncbf(s1[0]), s1[1] - truncbf(s1[1]));
            pl[3] = packbf2(s1[2] - truncbf(s1[2]), s1[3] - truncbf(s1[3]));
#pragma unroll
            for (int n2 = 0; n2 < 8; n2++) {
                uint32_t fvh[4], fvl[4];
                ldsm_x4_t(fvh, kvb + VHI_O + (kk * 16 + la) * AROWB + n2 * 32 + lah * 16);
                ldsm_x4_t(fvl, kvb + VLO_O + (kk * 16 + la) * AROWB + n2 * 32 + lah * 16);
                mma16816(O[2 * n2],     ph, fvh);
                mma16816(O[2 * n2],     ph, fvl);
                mma16816(O[2 * n2],     pl, fvh);
                mma16816(O[2 * n2 + 1], ph, fvh + 2);
                mma16816(O[2 * n2 + 1], ph, fvl + 2);
                mma16816(O[2 * n2 + 1], pl, fvh + 2);
            }
        }
        __syncthreads();
        if (kb + 2 < nkb) fillKV(cur, kb + 2);
    }

    // ---- epilogue: O/l, split to bf16 hi/lo ----
    l0 += __shfl_xor_sync(0xffffffffu, l0, 1);
    l0 += __shfl_xor_sync(0xffffffffu, l0, 2);
    l1 += __shfl_xor_sync(0xffffffffu, l1, 1);
    l1 += __shfl_xor_sync(0xffffffffu, l1, 2);
    const float i0 = 1.f / l0, i1 = 1.f / l1;
    const size_t o0 = ((size_t)b * S_ + grow) * C_ + h * HD + (lane & 3) * 2;
    const size_t o1 = o0 + 8 * C_;
#pragma unroll
    for (int nf = 0; nf < 16; nf++) {
        float v0 = O[nf][0] * i0, v1 = O[nf][1] * i0;
        float v2 = O[nf][2] * i1, v3 = O[nf][3] * i1;
        *(uint32_t*)(yhi + o0 + nf * 8) = packhi2(v0, v1);
        *(uint32_t*)(ylo + o0 + nf * 8) = packbf2(v0 - truncbf(v0), v1 - truncbf(v1));
        *(uint32_t*)(yhi + o1 + nf * 8) = packhi2(v2, v3);
        *(uint32_t*)(ylo + o1 + nf * 8) = packbf2(v2 - truncbf(v2), v3 - truncbf(v3));
    }
}

// ---------------------------------------------------------------------------
extern "C" void kernel_launch(void* const* d_in, const int* in_sizes, int n_in,
                              void* d_out, int out_size) {
    const float* x  = (const float*)d_in[0];
    const float* Wa = (const float*)d_in[1];
    const float* Wp = (const float*)d_in[2];
    float* out = (float*)d_out;

    __nv_bfloat16 *qkvhi, *qkvlo, *xhi, *xlo, *yhi, *ylo, *wahi, *walo, *wphi, *wplo;
    cudaGetSymbolAddress((void**)&qkvhi, g_qkvhi);
    cudaGetSymbolAddress((void**)&qkvlo, g_qkvlo);
    cudaGetSymbolAddress((void**)&xhi, g_xhi);
    cudaGetSymbolAddress((void**)&xlo, g_xlo);
    cudaGetSymbolAddress((void**)&yhi, g_yhi);
    cudaGetSymbolAddress((void**)&ylo, g_ylo);
    cudaGetSymbolAddress((void**)&wahi, g_wahi);
    cudaGetSymbolAddress((void**)&walo, g_walo);
    cudaGetSymbolAddress((void**)&wphi, g_wphi);
    cudaGetSymbolAddress((void**)&wplo, g_wplo);

    cudaFuncSetAttribute(gemm_hmma_kernel, cudaFuncAttributeMaxDynamicSharedMemorySize, GEMM_SMEM);
    cudaFuncSetAttribute(attn_mma_kernel, cudaFuncAttributeMaxDynamicSharedMemorySize, ATTN_SMEM);

    // 0) split/transpose operands
    int n4 = (MTOT * C_) / 4;
    split_kernel<<<(n4 + 255) / 256, 256>>>(x, xhi, xlo, n4);
    dim3 bT(32, 8);
    tsplit_kernel<<<dim3(QKV_LD / 32, C_ / 32), bT>>>(Wa, wahi, walo, C_, QKV_LD);
    tsplit_kernel<<<dim3(C_ / 32, C_ / 32), bT>>>(Wp, wphi, wplo, C_, C_);

    // 1) QKV projection -> bf16 hi/lo directly
    gemm_hmma_kernel<<<dim3(QKV_LD / 128, MTOT / 128), 256, GEMM_SMEM>>>(
        xhi, xlo, wahi, walo, nullptr, qkvhi, qkvlo, MTOT, QKV_LD, C_);

    // 2) Causal flash attention (tensor cores) -> y hi/lo
    attn_mma_kernel<<<dim3(16, B_ * NH), 256, ATTN_SMEM>>>(qkvhi, qkvlo, yhi, ylo);

    // 3) Output projection -> fp32 out
    gemm_hmma_kernel<<<dim3(C_ / 128, MTOT / 128), 256, GEMM_SMEM>>>(
        yhi, ylo, wphi, wplo, out, nullptr, nullptr, MTOT, C_, C_);
}

// round 12
// speedup vs baseline: 1.3660x; 1.0207x over previous
#include <cuda_runtime.h>
#include <cuda_bf16.h>
#include <cstdint>
#include <math.h>

// Problem constants
#define B_   4
#define S_   2048
#define C_   2048
#define NH   16
#define HD   128
#define QKV_LD 6144
#define MTOT (B_ * S_)          // 8192

// ---------------------------------------------------------------------------
// Scratch (__device__ globals — allocation-free rule)
// ---------------------------------------------------------------------------
__device__ __nv_bfloat16 g_qkvhi[(size_t)MTOT * QKV_LD];
__device__ __nv_bfloat16 g_qkvlo[(size_t)MTOT * QKV_LD];
__device__ __nv_bfloat16 g_xhi[(size_t)MTOT * C_];
__device__ __nv_bfloat16 g_xlo[(size_t)MTOT * C_];
__device__ __nv_bfloat16 g_yhi[(size_t)MTOT * C_];
__device__ __nv_bfloat16 g_ylo[(size_t)MTOT * C_];
__device__ __nv_bfloat16 g_wahi[(size_t)QKV_LD * C_];     // W_attn^T [6144,2048]
__device__ __nv_bfloat16 g_walo[(size_t)QKV_LD * C_];
__device__ __nv_bfloat16 g_wphi[(size_t)C_ * C_];         // W_proj^T [2048,2048]
__device__ __nv_bfloat16 g_wplo[(size_t)C_ * C_];

// ---------------------------------------------------------------------------
// PTX helpers (base compute_103 ISA: cp.async / ldmatrix / mma.sync)
// ---------------------------------------------------------------------------
__device__ __forceinline__ uint32_t smem_to_u32(const void* p) {
    uint32_t a;
    asm("{ .reg .u64 t; cvta.to.shared.u64 t, %1; cvt.u32.u64 %0, t; }" : "=r"(a) : "l"(p));
    return a;
}
__device__ __forceinline__ void cp16(uint32_t dst, const void* src) {
    asm volatile("cp.async.cg.shared.global [%0], [%1], 16;" :: "r"(dst), "l"(src));
}
#define CP_COMMIT() asm volatile("cp.async.commit_group;" ::: "memory")
#define CP_WAIT(n)  asm volatile("cp.async.wait_group %0;" :: "n"(n) : "memory")

__device__ __forceinline__ void ldsm_x4(uint32_t r[4], uint32_t addr) {
    asm volatile("ldmatrix.sync.aligned.m8n8.x4.shared.b16 {%0,%1,%2,%3}, [%4];"
        : "=r"(r[0]), "=r"(r[1]), "=r"(r[2]), "=r"(r[3]) : "r"(addr));
}
__device__ __forceinline__ void ldsm_x4_t(uint32_t r[4], uint32_t addr) {
    asm volatile("ldmatrix.sync.aligned.m8n8.x4.trans.shared.b16 {%0,%1,%2,%3}, [%4];"
        : "=r"(r[0]), "=r"(r[1]), "=r"(r[2]), "=r"(r[3]) : "r"(addr));
}
__device__ __forceinline__ void mma16816(float d[4], const uint32_t a[4], const uint32_t b[2]) {
    asm volatile(
        "mma.sync.aligned.m16n8k16.row.col.f32.bf16.bf16.f32 "
        "{%0,%1,%2,%3}, {%4,%5,%6,%7}, {%8,%9}, {%0,%1,%2,%3};"
        : "+f"(d[0]), "+f"(d[1]), "+f"(d[2]), "+f"(d[3])
        : "r"(a[0]), "r"(a[1]), "r"(a[2]), "r"(a[3]), "r"(b[0]), "r"(b[1]));
}
__device__ __forceinline__ float ex2f(float x) {
    float y; asm("ex2.approx.f32 %0, %1;" : "=f"(y) : "f"(x)); return y;
}
__device__ __forceinline__ uint32_t packhi2(float v0, float v1) {
    uint32_t r;
    asm("prmt.b32 %0, %1, %2, 0x7632;" : "=r"(r) : "r"(__float_as_uint(v0)), "r"(__float_as_uint(v1)));
    return r;
}
__device__ __forceinline__ float truncbf(float v) {
    return __uint_as_float(__float_as_uint(v) & 0xFFFF0000u);
}
__device__ __forceinline__ uint32_t packbf2(float lo, float hi) {
    uint32_t r;
    asm("cvt.rn.bf16x2.f32 %0, %1, %2;" : "=r"(r) : "f"(hi), "f"(lo));
    return r;
}

// ---------------------------------------------------------------------------
// Split fp32 -> (bf16 hi, bf16 lo)
// ---------------------------------------------------------------------------
__global__ void split_kernel(const float* __restrict__ in,
                             __nv_bfloat16* __restrict__ hi,
                             __nv_bfloat16* __restrict__ lo, int n4) {
    int i = blockIdx.x * blockDim.x + threadIdx.x;
    if (i >= n4) return;
    float4 v = ((const float4*)in)[i];
    float vv[4] = {v.x, v.y, v.z, v.w};
    __nv_bfloat16 h[4], l[4];
#pragma unroll
    for (int j = 0; j < 4; j++) {
        h[j] = __float2bfloat16(vv[j]);
        l[j] = __float2bfloat16(vv[j] - __bfloat162float(h[j]));
    }
    ((uint2*)hi)[i] = *(uint2*)h;
    ((uint2*)lo)[i] = *(uint2*)l;
}

// Transpose + split: in[K,N] fp32 -> hi/lo [N,K] bf16
__global__ void tsplit_kernel(const float* __restrict__ in,
                              __nv_bfloat16* __restrict__ hi,
                              __nv_bfloat16* __restrict__ lo, int K, int N) {
    __shared__ float t[32][33];
    int n0 = blockIdx.x * 32, k0 = blockIdx.y * 32;
    int tx = threadIdx.x, ty = threadIdx.y;
    for (int i = ty; i < 32; i += 8)
        t[i][tx] = in[(size_t)(k0 + i) * N + n0 + tx];
    __syncthreads();
    for (int i = ty; i < 32; i += 8) {
        float v = t[tx][i];
        __nv_bfloat16 h = __float2bfloat16(v);
        __nv_bfloat16 l = __float2bfloat16(v - __bfloat162float(h));
        size_t o = (size_t)(n0 + i) * K + k0 + tx;
        hi[o] = h;
        lo[o] = l;
    }
}

// ---------------------------------------------------------------------------
// HMMA split-precision GEMM (exact R9 — best measured): C = A @ B^T
// CTA 128x128, BK=32, 3-stage XOR-swizzled smem, 256 threads = 8 warps as
// 4x2 (warp tile 32x64), 2 CTAs/SM so barriers only stall half the SM.
// acc += Ahi*Bhi + Ahi*Blo + Alo*Bhi.
// Swizzle: 16B chunk c of row r stored at r*64 + ((c ^ ((r>>1)&3))*16).
// ---------------------------------------------------------------------------
#define GA_T   (128 * 64)                // 8192
#define GB_T   (128 * 64)                // 8192
#define GSTG   (2 * GA_T + 2 * GB_T)     // 32768
#define GEMM_SMEM (3 * GSTG)             // 98304

__global__ void __launch_bounds__(256, 2) gemm_hmma_kernel(
    const __nv_bfloat16* __restrict__ Ahi, const __nv_bfloat16* __restrict__ Alo,
    const __nv_bfloat16* __restrict__ Bhi, const __nv_bfloat16* __restrict__ Blo,
    float* __restrict__ C, __nv_bfloat16* __restrict__ Chi, __nv_bfloat16* __restrict__ Clo,
    int M, int N, int K)
{
    extern __shared__ char smem[];
    const uint32_t smb = smem_to_u32(smem);
    const int tid = threadIdx.x;
    const int wid = tid >> 5, lane = tid & 31;
    const int brow = blockIdx.y, bcol = blockIdx.x;
    const int NK = K >> 5;

    auto fill = [&](int st, int kt) {
        uint32_t sb = smb + st * GSTG;
        const int kof = kt * 32;
#pragma unroll
        for (int t = 0; t < 2; t++) {
            int idx = tid + t * 256;
            int r = idx >> 2, c = idx & 3;
            uint32_t off = r * 64 + ((c ^ ((r >> 1) & 3)) << 4);
            size_t gA = (size_t)(brow * 128 + r) * K + kof + c * 8;
            size_t gB = (size_t)(bcol * 128 + r) * K + kof + c * 8;
            cp16(sb + off, Ahi + gA);
            cp16(sb + GA_T + off, Alo + gA);
            cp16(sb + 2 * GA_T + off, Bhi + gB);
            cp16(sb + 2 * GA_T + GB_T + off, Blo + gB);
        }
        CP_COMMIT();
    };

    float acc[2][8][4];
#pragma unroll
    for (int mf = 0; mf < 2; mf++)
#pragma unroll
        for (int nf = 0; nf < 8; nf++)
#pragma unroll
            for (int e = 0; e < 4; e++) acc[mf][nf][e] = 0.f;

    const int wm = wid & 3, wn = wid >> 2;       // 4 x 2 warp grid
    const int la = lane & 15, lah = lane >> 4;
    const int lbn2 = (lane & 7) + ((lane >> 4) << 3);
    const int lbkc = (lane >> 3) & 1;

    const int rowA = wm * 32 + la;
    const int keyA = (rowA >> 1) & 3;
    const int rowB = wn * 64 + lbn2;
    const int keyB = (rowB >> 1) & 3;

    fill(0, 0);
    fill(1, 1);

    auto compute = [&](int kt) {
        uint32_t sb = smb + (kt % 3) * GSTG;
        uint32_t baseA = sb + rowA * 64;
        uint32_t baseB = sb + 2 * GA_T + rowB * 64;
#pragma unroll
        for (int ks = 0; ks < 2; ks++) {
            const uint32_t cAo = (uint32_t)(((ks * 2 + lah) ^ keyA) << 4);
            const uint32_t cBo = (uint32_t)(((ks * 2 + lbkc) ^ keyB) << 4);
            uint32_t fah[2][4], fal[2][4];
#pragma unroll
            for (int mf = 0; mf < 2; mf++) {
                ldsm_x4(fah[mf], baseA + mf * 1024 + cAo);
                ldsm_x4(fal[mf], baseA + GA_T + mf * 1024 + cAo);
            }
#pragma unroll
            for (int np = 0; np < 4; np++) {
                uint32_t fbh[4], fbl[4];
                ldsm_x4(fbh, baseB + np * 1024 + cBo);
                ldsm_x4(fbl, baseB + GB_T + np * 1024 + cBo);
#pragma unroll
                for (int mf = 0; mf < 2; mf++) {
                    mma16816(acc[mf][2 * np],     fah[mf], fbh);
                    mma16816(acc[mf][2 * np],     fah[mf], fbl);
                    mma16816(acc[mf][2 * np],     fal[mf], fbh);
                    mma16816(acc[mf][2 * np + 1], fah[mf], fbh + 2);
                    mma16816(acc[mf][2 * np + 1], fah[mf], fbl + 2);
                    mma16816(acc[mf][2 * np + 1], fal[mf], fbh + 2);
                }
            }
        }
    };

    for (int kt = 0; kt < NK; kt++) {
        CP_WAIT(1);                 // stage kt resident (kt+1 may be in flight)
        __syncthreads();
        if (kt + 2 < NK) fill((kt + 2) % 3, kt + 2);
        else CP_COMMIT();
        compute(kt);
    }

    // Epilogue
    const int r0 = brow * 128 + wm * 32 + (lane >> 2);
    const int c0 = bcol * 128 + wn * 64 + (lane & 3) * 2;
    if (C) {
#pragma unroll
        for (int mf = 0; mf < 2; mf++)
#pragma unroll
            for (int nf = 0; nf < 8; nf++) {
                int row = r0 + mf * 16, col = c0 + nf * 8;
                *(float2*)&C[(size_t)row * N + col] = make_float2(acc[mf][nf][0], acc[mf][nf][1]);
                *(float2*)&C[(size_t)(row + 8) * N + col] = make_float2(acc[mf][nf][2], acc[mf][nf][3]);
            }
    } else {
#pragma unroll
        for (int mf = 0; mf < 2; mf++)
#pragma unroll
            for (int nf = 0; nf < 8; nf++) {
                int row = r0 + mf * 16, col = c0 + nf * 8;
                float* a = acc[mf][nf];
                float h0 = truncbf(a[0]), h1 = truncbf(a[1]), h2 = truncbf(a[2]), h3 = truncbf(a[3]);
                *(uint32_t*)&Chi[(size_t)row * N + col] = packhi2(a[0], a[1]);
                *(uint32_t*)&Chi[(size_t)(row + 8) * N + col] = packhi2(a[2], a[3]);
                *(uint32_t*)&Clo[(size_t)row * N + col] = packbf2(a[0] - h0, a[1] - h1);
                *(uint32_t*)&Clo[(size_t)(row + 8) * N + col] = packbf2(a[2] - h2, a[3] - h3);
            }
    }
}

// ---------------------------------------------------------------------------
// Causal flash attention on tensor cores (bf16 hi/lo split precision).
// CTA = 128 q rows of one (b,h); 8 warps, each warp 16 full rows.
// Q fragments held in registers (loaded once); 3-stage KV pipeline with a
// single __syncthreads per kv-block.
// ---------------------------------------------------------------------------
#define AROWB 272                        // 128 bf16 = 256B + 16B pad
#define KHI_O 0
#define KLO_O (64 * AROWB)               // 17408
#define VHI_O (2 * 64 * AROWB)
#define VLO_O (3 * 64 * AROWB)
#define STG_SZ (4 * 64 * AROWB)          // 69632
#define ATTN_SMEM (3 * STG_SZ)           // 208896

__global__ void __launch_bounds__(256, 1) attn_mma_kernel(
    const __nv_bfloat16* __restrict__ qhv, const __nv_bfloat16* __restrict__ qlv,
    __nv_bfloat16* __restrict__ yhi, __nv_bfloat16* __restrict__ ylo)
{
    extern __shared__ char smem[];
    const uint32_t smb = smem_to_u32(smem);
    const int tid = threadIdx.x, wid = tid >> 5, lane = tid & 31;
    const int qb = 15 - blockIdx.x;              // heavy CTAs first
    const int bh = blockIdx.y, b = bh >> 4, h = bh & 15;
    const int nkb = 2 * qb + 2;
    const size_t gbase = (size_t)b * S_ * QKV_LD + (size_t)h * HD;
    const float csc = 0.12752963413397017f;      // 1/sqrt(128) * log2(e)

    // ---- Prologue: stage Q in stage-2's smem, ldsm into registers ----
    const uint32_t qsb = smb + 2 * STG_SZ;       // Q hi rows 0-127, lo at +128*AROWB
#pragma unroll
    for (int t = 0; t < 8; t++) {
        int idx = tid + t * 256;                 // 0..2047
        int r = idx >> 4, c = idx & 15;
        size_t g = gbase + (size_t)(qb * 128 + r) * QKV_LD + c * 8;
        cp16(qsb + r * AROWB + c * 16, qhv + g);
        cp16(qsb + 128 * AROWB + r * AROWB + c * 16, qlv + g);
    }
    CP_COMMIT();

    const int la = lane & 15, lah = lane >> 4;
    const int lbn2 = (lane & 7) + ((lane >> 4) << 3);
    const int lbk2 = ((lane >> 3) & 1) * 16;
    const int grow = qb * 128 + wid * 16 + (lane >> 2);

    CP_WAIT(0);
    __syncthreads();
    uint32_t Qh[8][4], Ql[8][4];
    {
        const uint32_t aQ = qsb + (wid * 16 + la) * AROWB + lah * 16;
#pragma unroll
        for (int ks = 0; ks < 8; ks++) {
            ldsm_x4(Qh[ks], aQ + ks * 32);
            ldsm_x4(Ql[ks], aQ + 128 * AROWB + ks * 32);
        }
    }
    __syncthreads();   // everyone done reading Q smem before stage 2 is recycled

    auto fillKV = [&](int kb) {
        uint32_t sb = smb + (kb % 3) * STG_SZ;
#pragma unroll
        for (int t = 0; t < 4; t++) {
            int idx = tid + t * 256;             // 0..1023
            int r = idx >> 4, c = idx & 15;
            size_t g = gbase + (size_t)(kb * 64 + r) * QKV_LD + c * 8;
            cp16(sb + KHI_O + r * AROWB + c * 16, qhv + g + C_);
            cp16(sb + KLO_O + r * AROWB + c * 16, qlv + g + C_);
            cp16(sb + VHI_O + r * AROWB + c * 16, qhv + g + 2 * C_);
            cp16(sb + VLO_O + r * AROWB + c * 16, qlv + g + 2 * C_);
        }
        CP_COMMIT();
    };
    fillKV(0);
    fillKV(1);

    float O[16][4];
#pragma unroll
    for (int nf = 0; nf < 16; nf++)
#pragma unroll
        for (int e = 0; e < 4; e++) O[nf][e] = 0.f;
    float m0 = -1e30f, m1 = -1e30f, l0 = 0.f, l1 = 0.f;

    for (int kb = 0; kb < nkb; kb++) {
        CP_WAIT(1);
        __syncthreads();             // stage kb visible; stage kb+2 (==kb-1) free
        if (kb + 2 < nkb) fillKV(kb + 2);
        const uint32_t kvb = smb + (kb % 3) * STG_SZ;
        const uint32_t aKh = kvb + KHI_O + lbn2 * AROWB + lbk2;
        const uint32_t aKl = kvb + KLO_O + lbn2 * AROWB + lbk2;

        // ---- S = Q K^T (scaled to base-2 domain) ----
        float S[8][4];
#pragma unroll
        for (int nf = 0; nf < 8; nf++)
#pragma unroll
            for (int e = 0; e < 4; e++) S[nf][e] = 0.f;

#pragma unroll
        for (int ks = 0; ks < 8; ks++) {
#pragma unroll
            for (int np = 0; np < 4; np++) {
                uint32_t fkh[4], fkl[4];
                ldsm_x4(fkh, aKh + np * 16 * AROWB + ks * 32);
                ldsm_x4(fkl, aKl + np * 16 * AROWB + ks * 32);
                mma16816(S[2 * np],     Qh[ks], fkh);
                mma16816(S[2 * np],     Qh[ks], fkl);
                mma16816(S[2 * np],     Ql[ks], fkh);
                mma16816(S[2 * np + 1], Qh[ks], fkh + 2);
                mma16816(S[2 * np + 1], Qh[ks], fkl + 2);
                mma16816(S[2 * np + 1], Ql[ks], fkh + 2);
            }
        }

        // ---- scale + causal mask ----
        const bool diag = (kb >= 2 * qb);
#pragma unroll
        for (int nf = 0; nf < 8; nf++)
#pragma unroll
            for (int e = 0; e < 4; e++) {
                float v = S[nf][e] * csc;
                if (diag) {
                    int col = kb * 64 + nf * 8 + (lane & 3) * 2 + (e & 1);
                    int row = grow + ((e & 2) ? 8 : 0);
                    if (col > row) v = -1e30f;
                }
                S[nf][e] = v;
            }

        // ---- online softmax ----
        float t0 = -1e30f, t1 = -1e30f;
#pragma unroll
        for (int nf = 0; nf < 8; nf++) {
            t0 = fmaxf(t0, fmaxf(S[nf][0], S[nf][1]));
            t1 = fmaxf(t1, fmaxf(S[nf][2], S[nf][3]));
        }
        t0 = fmaxf(t0, __shfl_xor_sync(0xffffffffu, t0, 1));
        t0 = fmaxf(t0, __shfl_xor_sync(0xffffffffu, t0, 2));
        t1 = fmaxf(t1, __shfl_xor_sync(0xffffffffu, t1, 1));
        t1 = fmaxf(t1, __shfl_xor_sync(0xffffffffu, t1, 2));
        float mn0 = fmaxf(m0, t0), mn1 = fmaxf(m1, t1);
        float a0 = ex2f(m0 - mn0), a1 = ex2f(m1 - mn1);
        m0 = mn0; m1 = mn1;
        float rs0 = 0.f, rs1 = 0.f;
#pragma unroll
        for (int nf = 0; nf < 8; nf++) {
            S[nf][0] = ex2f(S[nf][0] - mn0);
            S[nf][1] = ex2f(S[nf][1] - mn0);
            S[nf][2] = ex2f(S[nf][2] - mn1);
            S[nf][3] = ex2f(S[nf][3] - mn1);
            rs0 += S[nf][0] + S[nf][1];
            rs1 += S[nf][2] + S[nf][3];
        }
        l0 = l0 * a0 + rs0;
        l1 = l1 * a1 + rs1;
#pragma unroll
        for (int nf = 0; nf < 16; nf++) {
            O[nf][0] *= a0; O[nf][1] *= a0; O[nf][2] *= a1; O[nf][3] *= a1;
        }

        // ---- O += P V (P split hi/lo in registers) ----
#pragma unroll
        for (int kk = 0; kk < 4; kk++) {
            float* s0 = S[2 * kk];
            float* s1 = S[2 * kk + 1];
            uint32_t ph[4], pl[4];
            ph[0] = packhi2(s0[0], s0[1]);
            ph[1] = packhi2(s0[2], s0[3]);
            ph[2] = packhi2(s1[0], s1[1]);
            ph[3] = packhi2(s1[2], s1[3]);
            pl[0] = packbf2(s0[0] - truncbf(s0[0]), s0[1] - truncbf(s0[1]));
            pl[1] = packbf2(s0[2] - truncbf(s0[2]), s0[3] - truncbf(s0[3]));
            pl[2] = packbf2(s1[0] - truncbf(s1[0]), s1[1] - truncbf(s1[1]));
            pl[3] = packbf2(s1[2] - truncbf(s1[2]), s1[3] - truncbf(s1[3]));
#pragma unroll
            for (int n2 = 0; n2 < 8; n2++) {
                uint32_t fvh[4], fvl[4];
                ldsm_x4_t(fvh, kvb + VHI_O + (kk * 16 + la) * AROWB + n2 * 32 + lah * 16);
                ldsm_x4_t(fvl, kvb + VLO_O + (kk * 16 + la) * AROWB + n2 * 32 + lah * 16);
                mma16816(O[2 * n2],     ph, fvh);
                mma16816(O[2 * n2],     ph, fvl);
                mma16816(O[2 * n2],     pl, fvh);
                mma16816(O[2 * n2 + 1], ph, fvh + 2);
                mma16816(O[2 * n2 + 1], ph, fvl + 2);
                mma16816(O[2 * n2 + 1], pl, fvh + 2);
            }
        }
    }

    // ---- epilogue: O/l, split to bf16 hi/lo ----
    l0 += __shfl_xor_sync(0xffffffffu, l0, 1);
    l0 += __shfl_xor_sync(0xffffffffu, l0, 2);
    l1 += __shfl_xor_sync(0xffffffffu, l1, 1);
    l1 += __shfl_xor_sync(0xffffffffu, l1, 2);
    const float i0 = 1.f / l0, i1 = 1.f / l1;
    const size_t o0 = ((size_t)b * S_ + grow) * C_ + h * HD + (lane & 3) * 2;
    const size_t o1 = o0 + 8 * C_;
#pragma unroll
    for (int nf = 0; nf < 16; nf++) {
        float v0 = O[nf][0] * i0, v1 = O[nf][1] * i0;
        float v2 = O[nf][2] * i1, v3 = O[nf][3] * i1;
        *(uint32_t*)(yhi + o0 + nf * 8) = packhi2(v0, v1);
        *(uint32_t*)(ylo + o0 + nf * 8) = packbf2(v0 - truncbf(v0), v1 - truncbf(v1));
        *(uint32_t*)(yhi + o1 + nf * 8) = packhi2(v2, v3);
        *(uint32_t*)(ylo + o1 + nf * 8) = packbf2(v2 - truncbf(v2), v3 - truncbf(v3));
    }
}

// ---------------------------------------------------------------------------
extern "C" void kernel_launch(void* const* d_in, const int* in_sizes, int n_in,
                              void* d_out, int out_size) {
    const float* x  = (const float*)d_in[0];
    const float* Wa = (const float*)d_in[1];
    const float* Wp = (const float*)d_in[2];
    float* out = (float*)d_out;

    __nv_bfloat16 *qkvhi, *qkvlo, *xhi, *xlo, *yhi, *ylo, *wahi, *walo, *wphi, *wplo;
    cudaGetSymbolAddress((void**)&qkvhi, g_qkvhi);
    cudaGetSymbolAddress((void**)&qkvlo, g_qkvlo);
    cudaGetSymbolAddress((void**)&xhi, g_xhi);
    cudaGetSymbolAddress((void**)&xlo, g_xlo);
    cudaGetSymbolAddress((void**)&yhi, g_yhi);
    cudaGetSymbolAddress((void**)&ylo, g_ylo);
    cudaGetSymbolAddress((void**)&wahi, g_wahi);
    cudaGetSymbolAddress((void**)&walo, g_walo);
    cudaGetSymbolAddress((void**)&wphi, g_wphi);
    cudaGetSymbolAddress((void**)&wplo, g_wplo);

    cudaFuncSetAttribute(gemm_hmma_kernel, cudaFuncAttributeMaxDynamicSharedMemorySize, GEMM_SMEM);
    cudaFuncSetAttribute(attn_mma_kernel, cudaFuncAttributeMaxDynamicSharedMemorySize, ATTN_SMEM);

    // 0) split/transpose operands
    int n4 = (MTOT * C_) / 4;
    split_kernel<<<(n4 + 255) / 256, 256>>>(x, xhi, xlo, n4);
    dim3 bT(32, 8);
    tsplit_kernel<<<dim3(QKV_LD / 32, C_ / 32), bT>>>(Wa, wahi, walo, C_, QKV_LD);
    tsplit_kernel<<<dim3(C_ / 32, C_ / 32), bT>>>(Wp, wphi, wplo, C_, C_);

    // 1) QKV projection -> bf16 hi/lo directly
    gemm_hmma_kernel<<<dim3(QKV_LD / 128, MTOT / 128), 256, GEMM_SMEM>>>(
        xhi, xlo, wahi, walo, nullptr, qkvhi, qkvlo, MTOT, QKV_LD, C_);

    // 2) Causal flash attention (tensor cores) -> y hi/lo
    attn_mma_kernel<<<dim3(16, B_ * NH), 256, ATTN_SMEM>>>(qkvhi, qkvlo, yhi, ylo);

    // 3) Output projection -> fp32 out
    gemm_hmma_kernel<<<dim3(C_ / 128, MTOT / 128), 256, GEMM_SMEM>>>(
        yhi, ylo, wphi, wplo, out, nullptr, nullptr, MTOT, C_, C_);
}

// round 13
// speedup vs baseline: 1.4495x; 1.0611x over previous
#include <cuda_runtime.h>
#include <cuda_bf16.h>
#include <cstdint>
#include <math.h>

// Problem constants
#define B_   4
#define S_   2048
#define C_   2048
#define NH   16
#define HD   128
#define QKV_LD 6144
#define MTOT (B_ * S_)          // 8192

// ---------------------------------------------------------------------------
// Scratch (__device__ globals — allocation-free rule)
// ---------------------------------------------------------------------------
__device__ __nv_bfloat16 g_qkvhi[(size_t)MTOT * QKV_LD];
__device__ __nv_bfloat16 g_qkvlo[(size_t)MTOT * QKV_LD];
__device__ __nv_bfloat16 g_xhi[(size_t)MTOT * C_];
__device__ __nv_bfloat16 g_xlo[(size_t)MTOT * C_];
__device__ __nv_bfloat16 g_yhi[(size_t)MTOT * C_];
__device__ __nv_bfloat16 g_ylo[(size_t)MTOT * C_];
__device__ __nv_bfloat16 g_wahi[(size_t)QKV_LD * C_];     // W_attn^T [6144,2048]
__device__ __nv_bfloat16 g_walo[(size_t)QKV_LD * C_];
__device__ __nv_bfloat16 g_wphi[(size_t)C_ * C_];         // W_proj^T [2048,2048]
__device__ __nv_bfloat16 g_wplo[(size_t)C_ * C_];

// ---------------------------------------------------------------------------
// PTX helpers (base compute_103 ISA: cp.async / ldmatrix / mma.sync)
// ---------------------------------------------------------------------------
__device__ __forceinline__ uint32_t smem_to_u32(const void* p) {
    uint32_t a;
    asm("{ .reg .u64 t; cvta.to.shared.u64 t, %1; cvt.u32.u64 %0, t; }" : "=r"(a) : "l"(p));
    return a;
}
__device__ __forceinline__ void cp16(uint32_t dst, const void* src) {
    asm volatile("cp.async.cg.shared.global [%0], [%1], 16;" :: "r"(dst), "l"(src));
}
#define CP_COMMIT() asm volatile("cp.async.commit_group;" ::: "memory")
#define CP_WAIT(n)  asm volatile("cp.async.wait_group %0;" :: "n"(n) : "memory")

__device__ __forceinline__ void ldsm_x4(uint32_t r[4], uint32_t addr) {
    asm volatile("ldmatrix.sync.aligned.m8n8.x4.shared.b16 {%0,%1,%2,%3}, [%4];"
        : "=r"(r[0]), "=r"(r[1]), "=r"(r[2]), "=r"(r[3]) : "r"(addr));
}
__device__ __forceinline__ void ldsm_x4_t(uint32_t r[4], uint32_t addr) {
    asm volatile("ldmatrix.sync.aligned.m8n8.x4.trans.shared.b16 {%0,%1,%2,%3}, [%4];"
        : "=r"(r[0]), "=r"(r[1]), "=r"(r[2]), "=r"(r[3]) : "r"(addr));
}
__device__ __forceinline__ void mma16816(float d[4], const uint32_t a[4], const uint32_t b[2]) {
    asm volatile(
        "mma.sync.aligned.m16n8k16.row.col.f32.bf16.bf16.f32 "
        "{%0,%1,%2,%3}, {%4,%5,%6,%7}, {%8,%9}, {%0,%1,%2,%3};"
        : "+f"(d[0]), "+f"(d[1]), "+f"(d[2]), "+f"(d[3])
        : "r"(a[0]), "r"(a[1]), "r"(a[2]), "r"(a[3]), "r"(b[0]), "r"(b[1]));
}
__device__ __forceinline__ float ex2f(float x) {
    float y; asm("ex2.approx.f32 %0, %1;" : "=f"(y) : "f"(x)); return y;
}
__device__ __forceinline__ uint32_t packhi2(float v0, float v1) {
    uint32_t r;
    asm("prmt.b32 %0, %1, %2, 0x7632;" : "=r"(r) : "r"(__float_as_uint(v0)), "r"(__float_as_uint(v1)));
    return r;
}
__device__ __forceinline__ float truncbf(float v) {
    return __uint_as_float(__float_as_uint(v) & 0xFFFF0000u);
}
__device__ __forceinline__ uint32_t packbf2(float lo, float hi) {
    uint32_t r;
    asm("cvt.rn.bf16x2.f32 %0, %1, %2;" : "=r"(r) : "f"(hi), "f"(lo));
    return r;
}

// ---------------------------------------------------------------------------
// Split fp32 -> (bf16 hi, bf16 lo)
// ---------------------------------------------------------------------------
__global__ void split_kernel(const float* __restrict__ in,
                             __nv_bfloat16* __restrict__ hi,
                             __nv_bfloat16* __restrict__ lo, int n4) {
    int i = blockIdx.x * blockDim.x + threadIdx.x;
    if (i >= n4) return;
    float4 v = ((const float4*)in)[i];
    float vv[4] = {v.x, v.y, v.z, v.w};
    __nv_bfloat16 h[4], l[4];
#pragma unroll
    for (int j = 0; j < 4; j++) {
        h[j] = __float2bfloat16(vv[j]);
        l[j] = __float2bfloat16(vv[j] - __bfloat162float(h[j]));
    }
    ((uint2*)hi)[i] = *(uint2*)h;
    ((uint2*)lo)[i] = *(uint2*)l;
}

// Transpose + split: in[K,N] fp32 -> hi/lo [N,K] bf16
__global__ void tsplit_kernel(const float* __restrict__ in,
                              __nv_bfloat16* __restrict__ hi,
                              __nv_bfloat16* __restrict__ lo, int K, int N) {
    __shared__ float t[32][33];
    int n0 = blockIdx.x * 32, k0 = blockIdx.y * 32;
    int tx = threadIdx.x, ty = threadIdx.y;
    for (int i = ty; i < 32; i += 8)
        t[i][tx] = in[(size_t)(k0 + i) * N + n0 + tx];
    __syncthreads();
    for (int i = ty; i < 32; i += 8) {
        float v = t[tx][i];
        __nv_bfloat16 h = __float2bfloat16(v);
        __nv_bfloat16 l = __float2bfloat16(v - __bfloat162float(h));
        size_t o = (size_t)(n0 + i) * K + k0 + tx;
        hi[o] = h;
        lo[o] = l;
    }
}

// ---------------------------------------------------------------------------
// HMMA split-precision GEMM: C[M,N] = A[M,K] @ B[N,K]^T
// CTA 128x128, BK=32, 3-stage XOR-swizzled smem, 256 threads = 8 warps as
// 4x2 (warp tile 32x64), 2 CTAs/SM. fill() issued AFTER compute so cp.async
// issue overlaps the MMA drain instead of lengthening the post-barrier ramp.
// acc += Ahi*Bhi + Ahi*Blo + Alo*Bhi.
// Swizzle: 16B chunk c of row r stored at r*64 + ((c ^ ((r>>1)&3))*16).
// ---------------------------------------------------------------------------
#define GA_T   (128 * 64)                // 8192
#define GB_T   (128 * 64)                // 8192
#define GSTG   (2 * GA_T + 2 * GB_T)     // 32768
#define GEMM_SMEM (3 * GSTG)             // 98304

__global__ void __launch_bounds__(256, 2) gemm_hmma_kernel(
    const __nv_bfloat16* __restrict__ Ahi, const __nv_bfloat16* __restrict__ Alo,
    const __nv_bfloat16* __restrict__ Bhi, const __nv_bfloat16* __restrict__ Blo,
    float* __restrict__ C, __nv_bfloat16* __restrict__ Chi, __nv_bfloat16* __restrict__ Clo,
    int M, int N, int K)
{
    extern __shared__ char smem[];
    const uint32_t smb = smem_to_u32(smem);
    const int tid = threadIdx.x;
    const int wid = tid >> 5, lane = tid & 31;
    const int brow = blockIdx.y, bcol = blockIdx.x;
    const int NK = K >> 5;

    auto fill = [&](int st, int kt) {
        uint32_t sb = smb + st * GSTG;
        const int kof = kt * 32;
#pragma unroll
        for (int t = 0; t < 2; t++) {
            int idx = tid + t * 256;
            int r = idx >> 2, c = idx & 3;
            uint32_t off = r * 64 + ((c ^ ((r >> 1) & 3)) << 4);
            size_t gA = (size_t)(brow * 128 + r) * K + kof + c * 8;
            size_t gB = (size_t)(bcol * 128 + r) * K + kof + c * 8;
            cp16(sb + off, Ahi + gA);
            cp16(sb + GA_T + off, Alo + gA);
            cp16(sb + 2 * GA_T + off, Bhi + gB);
            cp16(sb + 2 * GA_T + GB_T + off, Blo + gB);
        }
        CP_COMMIT();
    };

    float acc[2][8][4];
#pragma unroll
    for (int mf = 0; mf < 2; mf++)
#pragma unroll
        for (int nf = 0; nf < 8; nf++)
#pragma unroll
            for (int e = 0; e < 4; e++) acc[mf][nf][e] = 0.f;

    const int wm = wid & 3, wn = wid >> 2;       // 4 x 2 warp grid
    const int la = lane & 15, lah = lane >> 4;
    const int lbn2 = (lane & 7) + ((lane >> 4) << 3);
    const int lbkc = (lane >> 3) & 1;

    const int rowA = wm * 32 + la;
    const int keyA = (rowA >> 1) & 3;
    const int rowB = wn * 64 + lbn2;
    const int keyB = (rowB >> 1) & 3;

    fill(0, 0);
    fill(1, 1);

    auto compute = [&](int kt) {
        uint32_t sb = smb + (kt % 3) * GSTG;
        uint32_t baseA = sb + rowA * 64;
        uint32_t baseB = sb + 2 * GA_T + rowB * 64;
#pragma unroll
        for (int ks = 0; ks < 2; ks++) {
            const uint32_t cAo = (uint32_t)(((ks * 2 + lah) ^ keyA) << 4);
            const uint32_t cBo = (uint32_t)(((ks * 2 + lbkc) ^ keyB) << 4);
            uint32_t fah[2][4], fal[2][4];
#pragma unroll
            for (int mf = 0; mf < 2; mf++) {
                ldsm_x4(fah[mf], baseA + mf * 1024 + cAo);
                ldsm_x4(fal[mf], baseA + GA_T + mf * 1024 + cAo);
            }
#pragma unroll
            for (int np = 0; np < 4; np++) {
                uint32_t fbh[4], fbl[4];
                ldsm_x4(fbh, baseB + np * 1024 + cBo);
                ldsm_x4(fbl, baseB + GB_T + np * 1024 + cBo);
#pragma unroll
                for (int mf = 0; mf < 2; mf++) {
                    mma16816(acc[mf][2 * np],     fah[mf], fbh);
                    mma16816(acc[mf][2 * np],     fah[mf], fbl);
                    mma16816(acc[mf][2 * np],     fal[mf], fbh);
                    mma16816(acc[mf][2 * np + 1], fah[mf], fbh + 2);
                    mma16816(acc[mf][2 * np + 1], fah[mf], fbl + 2);
                    mma16816(acc[mf][2 * np + 1], fal[mf], fbh + 2);
                }
            }
        }
    };

    for (int kt = 0; kt < NK; kt++) {
        CP_WAIT(1);                 // stage kt resident (kt+1 may be in flight)
        __syncthreads();            // all warps done reading stage (kt+2)%3
        compute(kt);                // MMAs start immediately after the barrier
        if (kt + 2 < NK) fill((kt + 2) % 3, kt + 2);   // overlaps MMA drain
        else CP_COMMIT();
    }

    // Epilogue
    const int r0 = brow * 128 + wm * 32 + (lane >> 2);
    const int c0 = bcol * 128 + wn * 64 + (lane & 3) * 2;
    if (C) {
#pragma unroll
        for (int mf = 0; mf < 2; mf++)
#pragma unroll
            for (int nf = 0; nf < 8; nf++) {
                int row = r0 + mf * 16, col = c0 + nf * 8;
                *(float2*)&C[(size_t)row * N + col] = make_float2(acc[mf][nf][0], acc[mf][nf][1]);
                *(float2*)&C[(size_t)(row + 8) * N + col] = make_float2(acc[mf][nf][2], acc[mf][nf][3]);
            }
    } else {
#pragma unroll
        for (int mf = 0; mf < 2; mf++)
#pragma unroll
            for (int nf = 0; nf < 8; nf++) {
                int row = r0 + mf * 16, col = c0 + nf * 8;
                float* a = acc[mf][nf];
                float h0 = truncbf(a[0]), h1 = truncbf(a[1]), h2 = truncbf(a[2]), h3 = truncbf(a[3]);
                *(uint32_t*)&Chi[(size_t)row * N + col] = packhi2(a[0], a[1]);
                *(uint32_t*)&Chi[(size_t)(row + 8) * N + col] = packhi2(a[2], a[3]);
                *(uint32_t*)&Clo[(size_t)row * N + col] = packbf2(a[0] - h0, a[1] - h1);
                *(uint32_t*)&Clo[(size_t)(row + 8) * N + col] = packbf2(a[2] - h2, a[3] - h3);
            }
    }
}

// ---------------------------------------------------------------------------
// Causal flash attention on tensor cores (bf16 hi/lo split precision).
// CTA = 128 q rows of one (b,h); 8 warps, each warp 16 full rows.
// Q fragments in registers (loaded once); 3-stage KV pipeline, one barrier
// per kv-block. Unchanged from R12.
// ---------------------------------------------------------------------------
#define AROWB 272                        // 128 bf16 = 256B + 16B pad
#define KHI_O 0
#define KLO_O (64 * AROWB)               // 17408
#define VHI_O (2 * 64 * AROWB)
#define VLO_O (3 * 64 * AROWB)
#define STG_SZ (4 * 64 * AROWB)          // 69632
#define ATTN_SMEM (3 * STG_SZ)           // 208896

__global__ void __launch_bounds__(256, 1) attn_mma_kernel(
    const __nv_bfloat16* __restrict__ qhv, const __nv_bfloat16* __restrict__ qlv,
    __nv_bfloat16* __restrict__ yhi, __nv_bfloat16* __restrict__ ylo)
{
    extern __shared__ char smem[];
    const uint32_t smb = smem_to_u32(smem);
    const int tid = threadIdx.x, wid = tid >> 5, lane = tid & 31;
    const int qb = 15 - blockIdx.x;              // heavy CTAs first
    const int bh = blockIdx.y, b = bh >> 4, h = bh & 15;
    const int nkb = 2 * qb + 2;
    const size_t gbase = (size_t)b * S_ * QKV_LD + (size_t)h * HD;
    const float csc = 0.12752963413397017f;      // 1/sqrt(128) * log2(e)

    // ---- Prologue: stage Q in stage-2's smem, ldsm into registers ----
    const uint32_t qsb = smb + 2 * STG_SZ;       // Q hi rows 0-127, lo at +128*AROWB
#pragma unroll
    for (int t = 0; t < 8; t++) {
        int idx = tid + t * 256;                 // 0..2047
        int r = idx >> 4, c = idx & 15;
        size_t g = gbase + (size_t)(qb * 128 + r) * QKV_LD + c * 8;
        cp16(qsb + r * AROWB + c * 16, qhv + g);
        cp16(qsb + 128 * AROWB + r * AROWB + c * 16, qlv + g);
    }
    CP_COMMIT();

    const int la = lane & 15, lah = lane >> 4;
    const int lbn2 = (lane & 7) + ((lane >> 4) << 3);
    const int lbk2 = ((lane >> 3) & 1) * 16;
    const int grow = qb * 128 + wid * 16 + (lane >> 2);

    CP_WAIT(0);
    __syncthreads();
    uint32_t Qh[8][4], Ql[8][4];
    {
        const uint32_t aQ = qsb + (wid * 16 + la) * AROWB + lah * 16;
#pragma unroll
        for (int ks = 0; ks < 8; ks++) {
            ldsm_x4(Qh[ks], aQ + ks * 32);
            ldsm_x4(Ql[ks], aQ + 128 * AROWB + ks * 32);
        }
    }
    __syncthreads();   // everyone done reading Q smem before stage 2 is recycled

    auto fillKV = [&](int kb) {
        uint32_t sb = smb + (kb % 3) * STG_SZ;
#pragma unroll
        for (int t = 0; t < 4; t++) {
            int idx = tid + t * 256;             // 0..1023
            int r = idx >> 4, c = idx & 15;
            size_t g = gbase + (size_t)(kb * 64 + r) * QKV_LD + c * 8;
            cp16(sb + KHI_O + r * AROWB + c * 16, qhv + g + C_);
            cp16(sb + KLO_O + r * AROWB + c * 16, qlv + g + C_);
            cp16(sb + VHI_O + r * AROWB + c * 16, qhv + g + 2 * C_);
            cp16(sb + VLO_O + r * AROWB + c * 16, qlv + g + 2 * C_);
        }
        CP_COMMIT();
    };
    fillKV(0);
    fillKV(1);

    float O[16][4];
#pragma unroll
    for (int nf = 0; nf < 16; nf++)
#pragma unroll
        for (int e = 0; e < 4; e++) O[nf][e] = 0.f;
    float m0 = -1e30f, m1 = -1e30f, l0 = 0.f, l1 = 0.f;

    for (int kb = 0; kb < nkb; kb++) {
        CP_WAIT(1);
        __syncthreads();             // stage kb visible; stage kb+2 (==kb-1) free
        if (kb + 2 < nkb) fillKV(kb + 2);
        const uint32_t kvb = smb + (kb % 3) * STG_SZ;
        const uint32_t aKh = kvb + KHI_O + lbn2 * AROWB + lbk2;
        const uint32_t aKl = kvb + KLO_O + lbn2 * AROWB + lbk2;

        // ---- S = Q K^T (scaled to base-2 domain) ----
        float S[8][4];
#pragma unroll
        for (int nf = 0; nf < 8; nf++)
#pragma unroll
            for (int e = 0; e < 4; e++) S[nf][e] = 0.f;

#pragma unroll
        for (int ks = 0; ks < 8; ks++) {
#pragma unroll
            for (int np = 0; np < 4; np++) {
                uint32_t fkh[4], fkl[4];
                ldsm_x4(fkh, aKh + np * 16 * AROWB + ks * 32);
                ldsm_x4(fkl, aKl + np * 16 * AROWB + ks * 32);
                mma16816(S[2 * np],     Qh[ks], fkh);
                mma16816(S[2 * np],     Qh[ks], fkl);
                mma16816(S[2 * np],     Ql[ks], fkh);
                mma16816(S[2 * np + 1], Qh[ks], fkh + 2);
                mma16816(S[2 * np + 1], Qh[ks], fkl + 2);
                mma16816(S[2 * np + 1], Ql[ks], fkh + 2);
            }
        }

        // ---- scale + causal mask ----
        const bool diag = (kb >= 2 * qb);
#pragma unroll
        for (int nf = 0; nf < 8; nf++)
#pragma unroll
            for (int e = 0; e < 4; e++) {
                float v = S[nf][e] * csc;
                if (diag) {
                    int col = kb * 64 + nf * 8 + (lane & 3) * 2 + (e & 1);
                    int row = grow + ((e & 2) ? 8 : 0);
                    if (col > row) v = -1e30f;
                }
                S[nf][e] = v;
            }

        // ---- online softmax ----
        float t0 = -1e30f, t1 = -1e30f;
#pragma unroll
        for (int nf = 0; nf < 8; nf++) {
            t0 = fmaxf(t0, fmaxf(S[nf][0], S[nf][1]));
            t1 = fmaxf(t1, fmaxf(S[nf][2], S[nf][3]));
        }
        t0 = fmaxf(t0, __shfl_xor_sync(0xffffffffu, t0, 1));
        t0 = fmaxf(t0, __shfl_xor_sync(0xffffffffu, t0, 2));
        t1 = fmaxf(t1, __shfl_xor_sync(0xffffffffu, t1, 1));
        t1 = fmaxf(t1, __shfl_xor_sync(0xffffffffu, t1, 2));
        float mn0 = fmaxf(m0, t0), mn1 = fmaxf(m1, t1);
        float a0 = ex2f(m0 - mn0), a1 = ex2f(m1 - mn1);
        m0 = mn0; m1 = mn1;
        float rs0 = 0.f, rs1 = 0.f;
#pragma unroll
        for (int nf = 0; nf < 8; nf++) {
            S[nf][0] = ex2f(S[nf][0] - mn0);
            S[nf][1] = ex2f(S[nf][1] - mn0);
            S[nf][2] = ex2f(S[nf][2] - mn1);
            S[nf][3] = ex2f(S[nf][3] - mn1);
            rs0 += S[nf][0] + S[nf][1];
            rs1 += S[nf][2] + S[nf][3];
        }
        l0 = l0 * a0 + rs0;
        l1 = l1 * a1 + rs1;
#pragma unroll
        for (int nf = 0; nf < 16; nf++) {
            O[nf][0] *= a0; O[nf][1] *= a0; O[nf][2] *= a1; O[nf][3] *= a1;
        }

        // ---- O += P V (P split hi/lo in registers) ----
#pragma unroll
        for (int kk = 0; kk < 4; kk++) {
            float* s0 = S[2 * kk];
            float* s1 = S[2 * kk + 1];
            uint32_t ph[4], pl[4];
            ph[0] = packhi2(s0[0], s0[1]);
            ph[1] = packhi2(s0[2], s0[3]);
            ph[2] = packhi2(s1[0], s1[1]);
            ph[3] = packhi2(s1[2], s1[3]);
            pl[0] = packbf2(s0[0] - truncbf(s0[0]), s0[1] - truncbf(s0[1]));
            pl[1] = packbf2(s0[2] - truncbf(s0[2]), s0[3] - truncbf(s0[3]));
            pl[2] = packbf2(s1[0] - truncbf(s1[0]), s1[1] - truncbf(s1[1]));
            pl[3] = packbf2(s1[2] - truncbf(s1[2]), s1[3] - truncbf(s1[3]));
#pragma unroll
            for (int n2 = 0; n2 < 8; n2++) {
                uint32_t fvh[4], fvl[4];
                ldsm_x4_t(fvh, kvb + VHI_O + (kk * 16 + la) * AROWB + n2 * 32 + lah * 16);
                ldsm_x4_t(fvl, kvb + VLO_O + (kk * 16 + la) * AROWB + n2 * 32 + lah * 16);
                mma16816(O[2 * n2],     ph, fvh);
                mma16816(O[2 * n2],     ph, fvl);
                mma16816(O[2 * n2],     pl, fvh);
                mma16816(O[2 * n2 + 1], ph, fvh + 2);
                mma16816(O[2 * n2 + 1], ph, fvl + 2);
                mma16816(O[2 * n2 + 1], pl, fvh + 2);
            }
        }
    }

    // ---- epilogue: O/l, split to bf16 hi/lo ----
    l0 += __shfl_xor_sync(0xffffffffu, l0, 1);
    l0 += __shfl_xor_sync(0xffffffffu, l0, 2);
    l1 += __shfl_xor_sync(0xffffffffu, l1, 1);
    l1 += __shfl_xor_sync(0xffffffffu, l1, 2);
    const float i0 = 1.f / l0, i1 = 1.f / l1;
    const size_t o0 = ((size_t)b * S_ + grow) * C_ + h * HD + (lane & 3) * 2;
    const size_t o1 = o0 + 8 * C_;
#pragma unroll
    for (int nf = 0; nf < 16; nf++) {
        float v0 = O[nf][0] * i0, v1 = O[nf][1] * i0;
        float v2 = O[nf][2] * i1, v3 = O[nf][3] * i1;
        *(uint32_t*)(yhi + o0 + nf * 8) = packhi2(v0, v1);
        *(uint32_t*)(ylo + o0 + nf * 8) = packbf2(v0 - truncbf(v0), v1 - truncbf(v1));
        *(uint32_t*)(yhi + o1 + nf * 8) = packhi2(v2, v3);
        *(uint32_t*)(ylo + o1 + nf * 8) = packbf2(v2 - truncbf(v2), v3 - truncbf(v3));
    }
}

// ---------------------------------------------------------------------------
extern "C" void kernel_launch(void* const* d_in, const int* in_sizes, int n_in,
                              void* d_out, int out_size) {
    const float* x  = (const float*)d_in[0];
    const float* Wa = (const float*)d_in[1];
    const float* Wp = (const float*)d_in[2];
    float* out = (float*)d_out;

    __nv_bfloat16 *qkvhi, *qkvlo, *xhi, *xlo, *yhi, *ylo, *wahi, *walo, *wphi, *wplo;
    cudaGetSymbolAddress((void**)&qkvhi, g_qkvhi);
    cudaGetSymbolAddress((void**)&qkvlo, g_qkvlo);
    cudaGetSymbolAddress((void**)&xhi, g_xhi);
    cudaGetSymbolAddress((void**)&xlo, g_xlo);
    cudaGetSymbolAddress((void**)&yhi, g_yhi);
    cudaGetSymbolAddress((void**)&ylo, g_ylo);
    cudaGetSymbolAddress((void**)&wahi, g_wahi);
    cudaGetSymbolAddress((void**)&walo, g_walo);
    cudaGetSymbolAddress((void**)&wphi, g_wphi);
    cudaGetSymbolAddress((void**)&wplo, g_wplo);

    cudaFuncSetAttribute(gemm_hmma_kernel, cudaFuncAttributeMaxDynamicSharedMemorySize, GEMM_SMEM);
    cudaFuncSetAttribute(attn_mma_kernel, cudaFuncAttributeMaxDynamicSharedMemorySize, ATTN_SMEM);

    // 0) split/transpose operands
    int n4 = (MTOT * C_) / 4;
    split_kernel<<<(n4 + 255) / 256, 256>>>(x, xhi, xlo, n4);
    dim3 bT(32, 8);
    tsplit_kernel<<<dim3(QKV_LD / 32, C_ / 32), bT>>>(Wa, wahi, walo, C_, QKV_LD);
    tsplit_kernel<<<dim3(C_ / 32, C_ / 32), bT>>>(Wp, wphi, wplo, C_, C_);

    // 1) QKV projection -> bf16 hi/lo directly
    gemm_hmma_kernel<<<dim3(QKV_LD / 128, MTOT / 128), 256, GEMM_SMEM>>>(
        xhi, xlo, wahi, walo, nullptr, qkvhi, qkvlo, MTOT, QKV_LD, C_);

    // 2) Causal flash attention (tensor cores) -> y hi/lo
    attn_mma_kernel<<<dim3(16, B_ * NH), 256, ATTN_SMEM>>>(qkvhi, qkvlo, yhi, ylo);

    // 3) Output projection -> fp32 out
    gemm_hmma_kernel<<<dim3(C_ / 128, MTOT / 128), 256, GEMM_SMEM>>>(
        yhi, ylo, wphi, wplo, out, nullptr, nullptr, MTOT, C_, C_);
}

// round 14
// speedup vs baseline: 1.4783x; 1.0199x over previous
#include <cuda_runtime.h>
#include <cuda_bf16.h>
#include <cstdint>
#include <math.h>

// Problem constants
#define B_   4
#define S_   2048
#define C_   2048
#define NH   16
#define HD   128
#define QKV_LD 6144
#define MTOT (B_ * S_)          // 8192

// ---------------------------------------------------------------------------
// Scratch (__device__ globals — allocation-free rule)
// ---------------------------------------------------------------------------
__device__ __nv_bfloat16 g_qkvhi[(size_t)MTOT * QKV_LD];
__device__ __nv_bfloat16 g_qkvlo[(size_t)MTOT * QKV_LD];
__device__ __nv_bfloat16 g_xhi[(size_t)MTOT * C_];
__device__ __nv_bfloat16 g_xlo[(size_t)MTOT * C_];
__device__ __nv_bfloat16 g_yhi[(size_t)MTOT * C_];
__device__ __nv_bfloat16 g_ylo[(size_t)MTOT * C_];
__device__ __nv_bfloat16 g_wahi[(size_t)QKV_LD * C_];     // W_attn^T [6144,2048]
__device__ __nv_bfloat16 g_walo[(size_t)QKV_LD * C_];
__device__ __nv_bfloat16 g_wphi[(size_t)C_ * C_];         // W_proj^T [2048,2048]
__device__ __nv_bfloat16 g_wplo[(size_t)C_ * C_];

// ---------------------------------------------------------------------------
// PTX helpers (base compute_103 ISA: cp.async / ldmatrix / mma.sync)
// ---------------------------------------------------------------------------
__device__ __forceinline__ uint32_t smem_to_u32(const void* p) {
    uint32_t a;
    asm("{ .reg .u64 t; cvta.to.shared.u64 t, %1; cvt.u32.u64 %0, t; }" : "=r"(a) : "l"(p));
    return a;
}
__device__ __forceinline__ void cp16(uint32_t dst, const void* src) {
    asm volatile("cp.async.cg.shared.global [%0], [%1], 16;" :: "r"(dst), "l"(src));
}
#define CP_COMMIT() asm volatile("cp.async.commit_group;" ::: "memory")
#define CP_WAIT(n)  asm volatile("cp.async.wait_group %0;" :: "n"(n) : "memory")

__device__ __forceinline__ void ldsm_x4(uint32_t r[4], uint32_t addr) {
    asm volatile("ldmatrix.sync.aligned.m8n8.x4.shared.b16 {%0,%1,%2,%3}, [%4];"
        : "=r"(r[0]), "=r"(r[1]), "=r"(r[2]), "=r"(r[3]) : "r"(addr));
}
__device__ __forceinline__ void ldsm_x4_t(uint32_t r[4], uint32_t addr) {
    asm volatile("ldmatrix.sync.aligned.m8n8.x4.trans.shared.b16 {%0,%1,%2,%3}, [%4];"
        : "=r"(r[0]), "=r"(r[1]), "=r"(r[2]), "=r"(r[3]) : "r"(addr));
}
__device__ __forceinline__ void mma16816(float d[4], const uint32_t a[4], const uint32_t b[2]) {
    asm volatile(
        "mma.sync.aligned.m16n8k16.row.col.f32.bf16.bf16.f32 "
        "{%0,%1,%2,%3}, {%4,%5,%6,%7}, {%8,%9}, {%0,%1,%2,%3};"
        : "+f"(d[0]), "+f"(d[1]), "+f"(d[2]), "+f"(d[3])
        : "r"(a[0]), "r"(a[1]), "r"(a[2]), "r"(a[3]), "r"(b[0]), "r"(b[1]));
}
__device__ __forceinline__ float ex2f(float x) {
    float y; asm("ex2.approx.f32 %0, %1;" : "=f"(y) : "f"(x)); return y;
}
__device__ __forceinline__ uint32_t packhi2(float v0, float v1) {
    uint32_t r;
    asm("prmt.b32 %0, %1, %2, 0x7632;" : "=r"(r) : "r"(__float_as_uint(v0)), "r"(__float_as_uint(v1)));
    return r;
}
__device__ __forceinline__ float truncbf(float v) {
    return __uint_as_float(__float_as_uint(v) & 0xFFFF0000u);
}
__device__ __forceinline__ uint32_t packbf2(float lo, float hi) {
    uint32_t r;
    asm("cvt.rn.bf16x2.f32 %0, %1, %2;" : "=r"(r) : "f"(hi), "f"(lo));
    return r;
}

// ---------------------------------------------------------------------------
// Split fp32 -> (bf16 hi, bf16 lo)
// ---------------------------------------------------------------------------
__global__ void split_kernel(const float* __restrict__ in,
                             __nv_bfloat16* __restrict__ hi,
                             __nv_bfloat16* __restrict__ lo, int n4) {
    int i = blockIdx.x * blockDim.x + threadIdx.x;
    if (i >= n4) return;
    float4 v = ((const float4*)in)[i];
    float vv[4] = {v.x, v.y, v.z, v.w};
    __nv_bfloat16 h[4], l[4];
#pragma unroll
    for (int j = 0; j < 4; j++) {
        h[j] = __float2bfloat16(vv[j]);
        l[j] = __float2bfloat16(vv[j] - __bfloat162float(h[j]));
    }
    ((uint2*)hi)[i] = *(uint2*)h;
    ((uint2*)lo)[i] = *(uint2*)l;
}

// Transpose + split: in[K,N] fp32 -> hi/lo [N,K] bf16
__global__ void tsplit_kernel(const float* __restrict__ in,
                              __nv_bfloat16* __restrict__ hi,
                              __nv_bfloat16* __restrict__ lo, int K, int N) {
    __shared__ float t[32][33];
    int n0 = blockIdx.x * 32, k0 = blockIdx.y * 32;
    int tx = threadIdx.x, ty = threadIdx.y;
    for (int i = ty; i < 32; i += 8)
        t[i][tx] = in[(size_t)(k0 + i) * N + n0 + tx];
    __syncthreads();
    for (int i = ty; i < 32; i += 8) {
        float v = t[tx][i];
        __nv_bfloat16 h = __float2bfloat16(v);
        __nv_bfloat16 l = __float2bfloat16(v - __bfloat162float(h));
        size_t o = (size_t)(n0 + i) * K + k0 + tx;
        hi[o] = h;
        lo[o] = l;
    }
}

// ---------------------------------------------------------------------------
// HMMA split-precision GEMM (exact R13 — best measured): C = A @ B^T
// CTA 128x128, BK=32, 3-stage XOR-swizzled smem, 256 threads = 8 warps as
// 4x2 (warp tile 32x64), 2 CTAs/SM. fill() after compute (overlaps MMA drain).
// acc += Ahi*Bhi + Ahi*Blo + Alo*Bhi.
// Swizzle: 16B chunk c of row r stored at r*64 + ((c ^ ((r>>1)&3))*16).
// ---------------------------------------------------------------------------
#define GA_T   (128 * 64)                // 8192
#define GB_T   (128 * 64)                // 8192
#define GSTG   (2 * GA_T + 2 * GB_T)     // 32768
#define GEMM_SMEM (3 * GSTG)             // 98304

__global__ void __launch_bounds__(256, 2) gemm_hmma_kernel(
    const __nv_bfloat16* __restrict__ Ahi, const __nv_bfloat16* __restrict__ Alo,
    const __nv_bfloat16* __restrict__ Bhi, const __nv_bfloat16* __restrict__ Blo,
    float* __restrict__ C, __nv_bfloat16* __restrict__ Chi, __nv_bfloat16* __restrict__ Clo,
    int M, int N, int K)
{
    extern __shared__ char smem[];
    const uint32_t smb = smem_to_u32(smem);
    const int tid = threadIdx.x;
    const int wid = tid >> 5, lane = tid & 31;
    const int brow = blockIdx.y, bcol = blockIdx.x;
    const int NK = K >> 5;

    auto fill = [&](int st, int kt) {
        uint32_t sb = smb + st * GSTG;
        const int kof = kt * 32;
#pragma unroll
        for (int t = 0; t < 2; t++) {
            int idx = tid + t * 256;
            int r = idx >> 2, c = idx & 3;
            uint32_t off = r * 64 + ((c ^ ((r >> 1) & 3)) << 4);
            size_t gA = (size_t)(brow * 128 + r) * K + kof + c * 8;
            size_t gB = (size_t)(bcol * 128 + r) * K + kof + c * 8;
            cp16(sb + off, Ahi + gA);
            cp16(sb + GA_T + off, Alo + gA);
            cp16(sb + 2 * GA_T + off, Bhi + gB);
            cp16(sb + 2 * GA_T + GB_T + off, Blo + gB);
        }
        CP_COMMIT();
    };

    float acc[2][8][4];
#pragma unroll
    for (int mf = 0; mf < 2; mf++)
#pragma unroll
        for (int nf = 0; nf < 8; nf++)
#pragma unroll
            for (int e = 0; e < 4; e++) acc[mf][nf][e] = 0.f;

    const int wm = wid & 3, wn = wid >> 2;       // 4 x 2 warp grid
    const int la = lane & 15, lah = lane >> 4;
    const int lbn2 = (lane & 7) + ((lane >> 4) << 3);
    const int lbkc = (lane >> 3) & 1;

    const int rowA = wm * 32 + la;
    const int keyA = (rowA >> 1) & 3;
    const int rowB = wn * 64 + lbn2;
    const int keyB = (rowB >> 1) & 3;

    fill(0, 0);
    fill(1, 1);

    auto compute = [&](int kt) {
        uint32_t sb = smb + (kt % 3) * GSTG;
        uint32_t baseA = sb + rowA * 64;
        uint32_t baseB = sb + 2 * GA_T + rowB * 64;
#pragma unroll
        for (int ks = 0; ks < 2; ks++) {
            const uint32_t cAo = (uint32_t)(((ks * 2 + lah) ^ keyA) << 4);
            const uint32_t cBo = (uint32_t)(((ks * 2 + lbkc) ^ keyB) << 4);
            uint32_t fah[2][4], fal[2][4];
#pragma unroll
            for (int mf = 0; mf < 2; mf++) {
                ldsm_x4(fah[mf], baseA + mf * 1024 + cAo);
                ldsm_x4(fal[mf], baseA + GA_T + mf * 1024 + cAo);
            }
#pragma unroll
            for (int np = 0; np < 4; np++) {
                uint32_t fbh[4], fbl[4];
                ldsm_x4(fbh, baseB + np * 1024 + cBo);
                ldsm_x4(fbl, baseB + GB_T + np * 1024 + cBo);
#pragma unroll
                for (int mf = 0; mf < 2; mf++) {
                    mma16816(acc[mf][2 * np],     fah[mf], fbh);
                    mma16816(acc[mf][2 * np],     fah[mf], fbl);
                    mma16816(acc[mf][2 * np],     fal[mf], fbh);
                    mma16816(acc[mf][2 * np + 1], fah[mf], fbh + 2);
                    mma16816(acc[mf][2 * np + 1], fah[mf], fbl + 2);
                    mma16816(acc[mf][2 * np + 1], fal[mf], fbh + 2);
                }
            }
        }
    };

    for (int kt = 0; kt < NK; kt++) {
        CP_WAIT(1);                 // stage kt resident (kt+1 may be in flight)
        __syncthreads();            // all warps done reading stage (kt+2)%3
        compute(kt);                // MMAs start immediately after the barrier
        if (kt + 2 < NK) fill((kt + 2) % 3, kt + 2);   // overlaps MMA drain
        else CP_COMMIT();
    }

    // Epilogue
    const int r0 = brow * 128 + wm * 32 + (lane >> 2);
    const int c0 = bcol * 128 + wn * 64 + (lane & 3) * 2;
    if (C) {
#pragma unroll
        for (int mf = 0; mf < 2; mf++)
#pragma unroll
            for (int nf = 0; nf < 8; nf++) {
                int row = r0 + mf * 16, col = c0 + nf * 8;
                *(float2*)&C[(size_t)row * N + col] = make_float2(acc[mf][nf][0], acc[mf][nf][1]);
                *(float2*)&C[(size_t)(row + 8) * N + col] = make_float2(acc[mf][nf][2], acc[mf][nf][3]);
            }
    } else {
#pragma unroll
        for (int mf = 0; mf < 2; mf++)
#pragma unroll
            for (int nf = 0; nf < 8; nf++) {
                int row = r0 + mf * 16, col = c0 + nf * 8;
                float* a = acc[mf][nf];
                float h0 = truncbf(a[0]), h1 = truncbf(a[1]), h2 = truncbf(a[2]), h3 = truncbf(a[3]);
                *(uint32_t*)&Chi[(size_t)row * N + col] = packhi2(a[0], a[1]);
                *(uint32_t*)&Chi[(size_t)(row + 8) * N + col] = packhi2(a[2], a[3]);
                *(uint32_t*)&Clo[(size_t)row * N + col] = packbf2(a[0] - h0, a[1] - h1);
                *(uint32_t*)&Clo[(size_t)(row + 8) * N + col] = packbf2(a[2] - h2, a[3] - h3);
            }
    }
}

// ---------------------------------------------------------------------------
// Causal flash attention on tensor cores (bf16 hi/lo split precision).
// CTA = 128 q rows of one (b,h); 8 warps, each warp 16 full rows.
// Q fragments in registers; 3-stage KV pipeline, one barrier per kv-block,
// fillKV issued AFTER the PV loop (overlaps MMA drain — R13 mechanism).
// ---------------------------------------------------------------------------
#define AROWB 272                        // 128 bf16 = 256B + 16B pad
#define KHI_O 0
#define KLO_O (64 * AROWB)               // 17408
#define VHI_O (2 * 64 * AROWB)
#define VLO_O (3 * 64 * AROWB)
#define STG_SZ (4 * 64 * AROWB)          // 69632
#define ATTN_SMEM (3 * STG_SZ)           // 208896

__global__ void __launch_bounds__(256, 1) attn_mma_kernel(
    const __nv_bfloat16* __restrict__ qhv, const __nv_bfloat16* __restrict__ qlv,
    __nv_bfloat16* __restrict__ yhi, __nv_bfloat16* __restrict__ ylo)
{
    extern __shared__ char smem[];
    const uint32_t smb = smem_to_u32(smem);
    const int tid = threadIdx.x, wid = tid >> 5, lane = tid & 31;
    const int qb = 15 - blockIdx.x;              // heavy CTAs first
    const int bh = blockIdx.y, b = bh >> 4, h = bh & 15;
    const int nkb = 2 * qb + 2;
    const size_t gbase = (size_t)b * S_ * QKV_LD + (size_t)h * HD;
    const float csc = 0.12752963413397017f;      // 1/sqrt(128) * log2(e)

    // ---- Prologue: stage Q in stage-2's smem, ldsm into registers ----
    const uint32_t qsb = smb + 2 * STG_SZ;       // Q hi rows 0-127, lo at +128*AROWB
#pragma unroll
    for (int t = 0; t < 8; t++) {
        int idx = tid + t * 256;                 // 0..2047
        int r = idx >> 4, c = idx & 15;
        size_t g = gbase + (size_t)(qb * 128 + r) * QKV_LD + c * 8;
        cp16(qsb + r * AROWB + c * 16, qhv + g);
        cp16(qsb + 128 * AROWB + r * AROWB + c * 16, qlv + g);
    }
    CP_COMMIT();

    const int la = lane & 15, lah = lane >> 4;
    const int lbn2 = (lane & 7) + ((lane >> 4) << 3);
    const int lbk2 = ((lane >> 3) & 1) * 16;
    const int grow = qb * 128 + wid * 16 + (lane >> 2);

    CP_WAIT(0);
    __syncthreads();
    uint32_t Qh[8][4], Ql[8][4];
    {
        const uint32_t aQ = qsb + (wid * 16 + la) * AROWB + lah * 16;
#pragma unroll
        for (int ks = 0; ks < 8; ks++) {
            ldsm_x4(Qh[ks], aQ + ks * 32);
            ldsm_x4(Ql[ks], aQ + 128 * AROWB + ks * 32);
        }
    }
    __syncthreads();   // everyone done reading Q smem before stage 2 is recycled

    auto fillKV = [&](int kb) {
        uint32_t sb = smb + (kb % 3) * STG_SZ;
#pragma unroll
        for (int t = 0; t < 4; t++) {
            int idx = tid + t * 256;             // 0..1023
            int r = idx >> 4, c = idx & 15;
            size_t g = gbase + (size_t)(kb * 64 + r) * QKV_LD + c * 8;
            cp16(sb + KHI_O + r * AROWB + c * 16, qhv + g + C_);
            cp16(sb + KLO_O + r * AROWB + c * 16, qlv + g + C_);
            cp16(sb + VHI_O + r * AROWB + c * 16, qhv + g + 2 * C_);
            cp16(sb + VLO_O + r * AROWB + c * 16, qlv + g + 2 * C_);
        }
        CP_COMMIT();
    };
    fillKV(0);
    fillKV(1);

    float O[16][4];
#pragma unroll
    for (int nf = 0; nf < 16; nf++)
#pragma unroll
        for (int e = 0; e < 4; e++) O[nf][e] = 0.f;
    float m0 = -1e30f, m1 = -1e30f, l0 = 0.f, l1 = 0.f;

    for (int kb = 0; kb < nkb; kb++) {
        CP_WAIT(1);
        __syncthreads();             // stage kb visible; stage (kb+2)%3 free
        const uint32_t kvb = smb + (kb % 3) * STG_SZ;
        const uint32_t aKh = kvb + KHI_O + lbn2 * AROWB + lbk2;
        const uint32_t aKl = kvb + KLO_O + lbn2 * AROWB + lbk2;

        // ---- S = Q K^T (scaled to base-2 domain) ----
        float S[8][4];
#pragma unroll
        for (int nf = 0; nf < 8; nf++)
#pragma unroll
            for (int e = 0; e < 4; e++) S[nf][e] = 0.f;

#pragma unroll
        for (int ks = 0; ks < 8; ks++) {
#pragma unroll
            for (int np = 0; np < 4; np++) {
                uint32_t fkh[4], fkl[4];
                ldsm_x4(fkh, aKh + np * 16 * AROWB + ks * 32);
                ldsm_x4(fkl, aKl + np * 16 * AROWB + ks * 32);
                mma16816(S[2 * np],     Qh[ks], fkh);
                mma16816(S[2 * np],     Qh[ks], fkl);
                mma16816(S[2 * np],     Ql[ks], fkh);
                mma16816(S[2 * np + 1], Qh[ks], fkh + 2);
                mma16816(S[2 * np + 1], Qh[ks], fkl + 2);
                mma16816(S[2 * np + 1], Ql[ks], fkh + 2);
            }
        }

        // ---- scale + causal mask ----
        const bool diag = (kb >= 2 * qb);
#pragma unroll
        for (int nf = 0; nf < 8; nf++)
#pragma unroll
            for (int e = 0; e < 4; e++) {
                float v = S[nf][e] * csc;
                if (diag) {
                    int col = kb * 64 + nf * 8 + (lane & 3) * 2 + (e & 1);
                    int row = grow + ((e & 2) ? 8 : 0);
                    if (col > row) v = -1e30f;
                }
                S[nf][e] = v;
            }

        // ---- online softmax ----
        float t0 = -1e30f, t1 = -1e30f;
#pragma unroll
        for (int nf = 0; nf < 8; nf++) {
            t0 = fmaxf(t0, fmaxf(S[nf][0], S[nf][1]));
            t1 = fmaxf(t1, fmaxf(S[nf][2], S[nf][3]));
        }
        t0 = fmaxf(t0, __shfl_xor_sync(0xffffffffu, t0, 1));
        t0 = fmaxf(t0, __shfl_xor_sync(0xffffffffu, t0, 2));
        t1 = fmaxf(t1, __shfl_xor_sync(0xffffffffu, t1, 1));
        t1 = fmaxf(t1, __shfl_xor_sync(0xffffffffu, t1, 2));
        float mn0 = fmaxf(m0, t0), mn1 = fmaxf(m1, t1);
        float a0 = ex2f(m0 - mn0), a1 = ex2f(m1 - mn1);
        m0 = mn0; m1 = mn1;
        float rs0 = 0.f, rs1 = 0.f;
#pragma unroll
        for (int nf = 0; nf < 8; nf++) {
            S[nf][0] = ex2f(S[nf][0] - mn0);
            S[nf][1] = ex2f(S[nf][1] - mn0);
            S[nf][2] = ex2f(S[nf][2] - mn1);
            S[nf][3] = ex2f(S[nf][3] - mn1);
            rs0 += S[nf][0] + S[nf][1];
            rs1 += S[nf][2] + S[nf][3];
        }
        l0 = l0 * a0 + rs0;
        l1 = l1 * a1 + rs1;
#pragma unroll
        for (int nf = 0; nf < 16; nf++) {
            O[nf][0] *= a0; O[nf][1] *= a0; O[nf][2] *= a1; O[nf][3] *= a1;
        }

        // ---- O += P V (P split hi/lo in registers) ----
#pragma unroll
        for (int kk = 0; kk < 4; kk++) {
            float* s0 = S[2 * kk];
            float* s1 = S[2 * kk + 1];
            uint32_t ph[4], pl[4];
            ph[0] = packhi2(s0[0], s0[1]);
            ph[1] = packhi2(s0[2], s0[3]);
            ph[2] = packhi2(s1[0], s1[1]);
            ph[3] = packhi2(s1[2], s1[3]);
            pl[0] = packbf2(s0[0] - truncbf(s0[0]), s0[1] - truncbf(s0[1]));
            pl[1] = packbf2(s0[2] - truncbf(s0[2]), s0[3] - truncbf(s0[3]));
            pl[2] = packbf2(s1[0] - truncbf(s1[0]), s1[1] - truncbf(s1[1]));
            pl[3] = packbf2(s1[2] - truncbf(s1[2]), s1[3] - truncbf(s1[3]));
#pragma unroll
            for (int n2 = 0; n2 < 8; n2++) {
                uint32_t fvh[4], fvl[4];
                ldsm_x4_t(fvh, kvb + VHI_O + (kk * 16 + la) * AROWB + n2 * 32 + lah * 16);
                ldsm_x4_t(fvl, kvb + VLO_O + (kk * 16 + la) * AROWB + n2 * 32 + lah * 16);
                mma16816(O[2 * n2],     ph, fvh);
                mma16816(O[2 * n2],     ph, fvl);
                mma16816(O[2 * n2],     pl, fvh);
                mma16816(O[2 * n2 + 1], ph, fvh + 2);
                mma16816(O[2 * n2 + 1], ph, fvl + 2);
                mma16816(O[2 * n2 + 1], pl, fvh + 2);
            }
        }

        // fill AFTER compute — cp.async issue overlaps the PV MMA drain
        if (kb + 2 < nkb) fillKV(kb + 2);
    }

    // ---- epilogue: O/l, split to bf16 hi/lo ----
    l0 += __shfl_xor_sync(0xffffffffu, l0, 1);
    l0 += __shfl_xor_sync(0xffffffffu, l0, 2);
    l1 += __shfl_xor_sync(0xffffffffu, l1, 1);
    l1 += __shfl_xor_sync(0xffffffffu, l1, 2);
    const float i0 = 1.f / l0, i1 = 1.f / l1;
    const size_t o0 = ((size_t)b * S_ + grow) * C_ + h * HD + (lane & 3) * 2;
    const size_t o1 = o0 + 8 * C_;
#pragma unroll
    for (int nf = 0; nf < 16; nf++) {
        float v0 = O[nf][0] * i0, v1 = O[nf][1] * i0;
        float v2 = O[nf][2] * i1, v3 = O[nf][3] * i1;
        *(uint32_t*)(yhi + o0 + nf * 8) = packhi2(v0, v1);
        *(uint32_t*)(ylo + o0 + nf * 8) = packbf2(v0 - truncbf(v0), v1 - truncbf(v1));
        *(uint32_t*)(yhi + o1 + nf * 8) = packhi2(v2, v3);
        *(uint32_t*)(ylo + o1 + nf * 8) = packbf2(v2 - truncbf(v2), v3 - truncbf(v3));
    }
}

// ---------------------------------------------------------------------------
extern "C" void kernel_launch(void* const* d_in, const int* in_sizes, int n_in,
                              void* d_out, int out_size) {
    const float* x  = (const float*)d_in[0];
    const float* Wa = (const float*)d_in[1];
    const float* Wp = (const float*)d_in[2];
    float* out = (float*)d_out;

    __nv_bfloat16 *qkvhi, *qkvlo, *xhi, *xlo, *yhi, *ylo, *wahi, *walo, *wphi, *wplo;
    cudaGetSymbolAddress((void**)&qkvhi, g_qkvhi);
    cudaGetSymbolAddress((void**)&qkvlo, g_qkvlo);
    cudaGetSymbolAddress((void**)&xhi, g_xhi);
    cudaGetSymbolAddress((void**)&xlo, g_xlo);
    cudaGetSymbolAddress((void**)&yhi, g_yhi);
    cudaGetSymbolAddress((void**)&ylo, g_ylo);
    cudaGetSymbolAddress((void**)&wahi, g_wahi);
    cudaGetSymbolAddress((void**)&walo, g_walo);
    cudaGetSymbolAddress((void**)&wphi, g_wphi);
    cudaGetSymbolAddress((void**)&wplo, g_wplo);

    cudaFuncSetAttribute(gemm_hmma_kernel, cudaFuncAttributeMaxDynamicSharedMemorySize, GEMM_SMEM);
    cudaFuncSetAttribute(attn_mma_kernel, cudaFuncAttributeMaxDynamicSharedMemorySize, ATTN_SMEM);

    // 0) split/transpose operands
    int n4 = (MTOT * C_) / 4;
    split_kernel<<<(n4 + 255) / 256, 256>>>(x, xhi, xlo, n4);
    dim3 bT(32, 8);
    tsplit_kernel<<<dim3(QKV_LD / 32, C_ / 32), bT>>>(Wa, wahi, walo, C_, QKV_LD);
    tsplit_kernel<<<dim3(C_ / 32, C_ / 32), bT>>>(Wp, wphi, wplo, C_, C_);

    // 1) QKV projection -> bf16 hi/lo directly
    gemm_hmma_kernel<<<dim3(QKV_LD / 128, MTOT / 128), 256, GEMM_SMEM>>>(
        xhi, xlo, wahi, walo, nullptr, qkvhi, qkvlo, MTOT, QKV_LD, C_);

    // 2) Causal flash attention (tensor cores) -> y hi/lo
    attn_mma_kernel<<<dim3(16, B_ * NH), 256, ATTN_SMEM>>>(qkvhi, qkvlo, yhi, ylo);

    // 3) Output projection -> fp32 out
    gemm_hmma_kernel<<<dim3(C_ / 128, MTOT / 128), 256, GEMM_SMEM>>>(
        yhi, ylo, wphi, wplo, out, nullptr, nullptr, MTOT, C_, C_);
}

// round 15
// speedup vs baseline: 1.6516x; 1.1172x over previous
#include <cuda_runtime.h>
#include <cuda_bf16.h>
#include <cuda_fp16.h>
#include <cstdint>
#include <math.h>

// Problem constants
#define B_   4
#define S_   2048
#define C_   2048
#define NH   16
#define HD   128
#define QKV_LD 6144
#define MTOT (B_ * S_)          // 8192

// ---------------------------------------------------------------------------
// Scratch (__device__ globals — allocation-free rule)
// ---------------------------------------------------------------------------
__device__ __nv_bfloat16 g_qkvhi[(size_t)MTOT * QKV_LD];
__device__ __nv_bfloat16 g_qkvlo[(size_t)MTOT * QKV_LD];
__device__ __nv_bfloat16 g_xhi[(size_t)MTOT * C_];
__device__ __nv_bfloat16 g_xlo[(size_t)MTOT * C_];
__device__ __half        g_y16[(size_t)MTOT * C_];        // attention out, fp16
__device__ __nv_bfloat16 g_wahi[(size_t)QKV_LD * C_];     // W_attn^T [6144,2048]
__device__ __nv_bfloat16 g_walo[(size_t)QKV_LD * C_];
__device__ __half        g_wp16[(size_t)C_ * C_];         // W_proj^T fp16

// ---------------------------------------------------------------------------
// PTX helpers (base compute_103 ISA: cp.async / ldmatrix / mma.sync)
// ---------------------------------------------------------------------------
__device__ __forceinline__ uint32_t smem_to_u32(const void* p) {
    uint32_t a;
    asm("{ .reg .u64 t; cvta.to.shared.u64 t, %1; cvt.u32.u64 %0, t; }" : "=r"(a) : "l"(p));
    return a;
}
__device__ __forceinline__ void cp16(uint32_t dst, const void* src) {
    asm volatile("cp.async.cg.shared.global [%0], [%1], 16;" :: "r"(dst), "l"(src));
}
#define CP_COMMIT() asm volatile("cp.async.commit_group;" ::: "memory")
#define CP_WAIT(n)  asm volatile("cp.async.wait_group %0;" :: "n"(n) : "memory")

__device__ __forceinline__ void ldsm_x4(uint32_t r[4], uint32_t addr) {
    asm volatile("ldmatrix.sync.aligned.m8n8.x4.shared.b16 {%0,%1,%2,%3}, [%4];"
        : "=r"(r[0]), "=r"(r[1]), "=r"(r[2]), "=r"(r[3]) : "r"(addr));
}
__device__ __forceinline__ void ldsm_x4_t(uint32_t r[4], uint32_t addr) {
    asm volatile("ldmatrix.sync.aligned.m8n8.x4.trans.shared.b16 {%0,%1,%2,%3}, [%4];"
        : "=r"(r[0]), "=r"(r[1]), "=r"(r[2]), "=r"(r[3]) : "r"(addr));
}
__device__ __forceinline__ void mma16816(float d[4], const uint32_t a[4], const uint32_t b[2]) {
    asm volatile(
        "mma.sync.aligned.m16n8k16.row.col.f32.bf16.bf16.f32 "
        "{%0,%1,%2,%3}, {%4,%5,%6,%7}, {%8,%9}, {%0,%1,%2,%3};"
        : "+f"(d[0]), "+f"(d[1]), "+f"(d[2]), "+f"(d[3])
        : "r"(a[0]), "r"(a[1]), "r"(a[2]), "r"(a[3]), "r"(b[0]), "r"(b[1]));
}
__device__ __forceinline__ void mma16816h(float d[4], const uint32_t a[4], const uint32_t b[2]) {
    asm volatile(
        "mma.sync.aligned.m16n8k16.row.col.f32.f16.f16.f32 "
        "{%0,%1,%2,%3}, {%4,%5,%6,%7}, {%8,%9}, {%0,%1,%2,%3};"
        : "+f"(d[0]), "+f"(d[1]), "+f"(d[2]), "+f"(d[3])
        : "r"(a[0]), "r"(a[1]), "r"(a[2]), "r"(a[3]), "r"(b[0]), "r"(b[1]));
}
__device__ __forceinline__ float ex2f(float x) {
    float y; asm("ex2.approx.f32 %0, %1;" : "=f"(y) : "f"(x)); return y;
}
__device__ __forceinline__ uint32_t packhi2(float v0, float v1) {
    uint32_t r;
    asm("prmt.b32 %0, %1, %2, 0x7632;" : "=r"(r) : "r"(__float_as_uint(v0)), "r"(__float_as_uint(v1)));
    return r;
}
__device__ __forceinline__ float truncbf(float v) {
    return __uint_as_float(__float_as_uint(v) & 0xFFFF0000u);
}
__device__ __forceinline__ uint32_t packbf2(float lo, float hi) {
    uint32_t r;
    asm("cvt.rn.bf16x2.f32 %0, %1, %2;" : "=r"(r) : "f"(hi), "f"(lo));
    return r;
}
__device__ __forceinline__ uint32_t packf16x2(float lo, float hi) {
    uint32_t r;
    asm("cvt.rn.f16x2.f32 %0, %1, %2;" : "=r"(r) : "f"(hi), "f"(lo));
    return r;
}

// ---------------------------------------------------------------------------
// Split fp32 -> (bf16 hi, bf16 lo)
// ---------------------------------------------------------------------------
__global__ void split_kernel(const float* __restrict__ in,
                             __nv_bfloat16* __restrict__ hi,
                             __nv_bfloat16* __restrict__ lo, int n4) {
    int i = blockIdx.x * blockDim.x + threadIdx.x;
    if (i >= n4) return;
    float4 v = ((const float4*)in)[i];
    float vv[4] = {v.x, v.y, v.z, v.w};
    __nv_bfloat16 h[4], l[4];
#pragma unroll
    for (int j = 0; j < 4; j++) {
        h[j] = __float2bfloat16(vv[j]);
        l[j] = __float2bfloat16(vv[j] - __bfloat162float(h[j]));
    }
    ((uint2*)hi)[i] = *(uint2*)h;
    ((uint2*)lo)[i] = *(uint2*)l;
}

// Transpose + split: in[K,N] fp32 -> hi/lo [N,K] bf16
__global__ void tsplit_kernel(const float* __restrict__ in,
                              __nv_bfloat16* __restrict__ hi,
                              __nv_bfloat16* __restrict__ lo, int K, int N) {
    __shared__ float t[32][33];
    int n0 = blockIdx.x * 32, k0 = blockIdx.y * 32;
    int tx = threadIdx.x, ty = threadIdx.y;
    for (int i = ty; i < 32; i += 8)
        t[i][tx] = in[(size_t)(k0 + i) * N + n0 + tx];
    __syncthreads();
    for (int i = ty; i < 32; i += 8) {
        float v = t[tx][i];
        __nv_bfloat16 h = __float2bfloat16(v);
        __nv_bfloat16 l = __float2bfloat16(v - __bfloat162float(h));
        size_t o = (size_t)(n0 + i) * K + k0 + tx;
        hi[o] = h;
        lo[o] = l;
    }
}

// Transpose + convert: in[K,N] fp32 -> fp16 [N,K]
__global__ void tcvt16_kernel(const float* __restrict__ in,
                              __half* __restrict__ out, int K, int N) {
    __shared__ float t[32][33];
    int n0 = blockIdx.x * 32, k0 = blockIdx.y * 32;
    int tx = threadIdx.x, ty = threadIdx.y;
    for (int i = ty; i < 32; i += 8)
        t[i][tx] = in[(size_t)(k0 + i) * N + n0 + tx];
    __syncthreads();
    for (int i = ty; i < 32; i += 8) {
        out[(size_t)(n0 + i) * K + k0 + tx] = __float2half(t[tx][i]);
    }
}

// ---------------------------------------------------------------------------
// HMMA split-precision bf16 GEMM (exact R13/R14 — best measured): C = A @ B^T
// CTA 128x128, BK=32, 3-stage XOR-swizzled smem, 256 threads = 8 warps as
// 4x2 (warp tile 32x64), 2 CTAs/SM. fill() after compute.
// acc += Ahi*Bhi + Ahi*Blo + Alo*Bhi.
// Swizzle: 16B chunk c of row r stored at r*64 + ((c ^ ((r>>1)&3))*16).
// ---------------------------------------------------------------------------
#define GA_T   (128 * 64)                // 8192
#define GB_T   (128 * 64)                // 8192
#define GSTG   (2 * GA_T + 2 * GB_T)     // 32768
#define GEMM_SMEM (3 * GSTG)             // 98304

__global__ void __launch_bounds__(256, 2) gemm_hmma_kernel(
    const __nv_bfloat16* __restrict__ Ahi, const __nv_bfloat16* __restrict__ Alo,
    const __nv_bfloat16* __restrict__ Bhi, const __nv_bfloat16* __restrict__ Blo,
    float* __restrict__ C, __nv_bfloat16* __restrict__ Chi, __nv_bfloat16* __restrict__ Clo,
    int M, int N, int K)
{
    extern __shared__ char smem[];
    const uint32_t smb = smem_to_u32(smem);
    const int tid = threadIdx.x;
    const int wid = tid >> 5, lane = tid & 31;
    const int brow = blockIdx.y, bcol = blockIdx.x;
    const int NK = K >> 5;

    auto fill = [&](int st, int kt) {
        uint32_t sb = smb + st * GSTG;
        const int kof = kt * 32;
#pragma unroll
        for (int t = 0; t < 2; t++) {
            int idx = tid + t * 256;
            int r = idx >> 2, c = idx & 3;
            uint32_t off = r * 64 + ((c ^ ((r >> 1) & 3)) << 4);
            size_t gA = (size_t)(brow * 128 + r) * K + kof + c * 8;
            size_t gB = (size_t)(bcol * 128 + r) * K + kof + c * 8;
            cp16(sb + off, Ahi + gA);
            cp16(sb + GA_T + off, Alo + gA);
            cp16(sb + 2 * GA_T + off, Bhi + gB);
            cp16(sb + 2 * GA_T + GB_T + off, Blo + gB);
        }
        CP_COMMIT();
    };

    float acc[2][8][4];
#pragma unroll
    for (int mf = 0; mf < 2; mf++)
#pragma unroll
        for (int nf = 0; nf < 8; nf++)
#pragma unroll
            for (int e = 0; e < 4; e++) acc[mf][nf][e] = 0.f;

    const int wm = wid & 3, wn = wid >> 2;       // 4 x 2 warp grid
    const int la = lane & 15, lah = lane >> 4;
    const int lbn2 = (lane & 7) + ((lane >> 4) << 3);
    const int lbkc = (lane >> 3) & 1;

    const int rowA = wm * 32 + la;
    const int keyA = (rowA >> 1) & 3;
    const int rowB = wn * 64 + lbn2;
    const int keyB = (rowB >> 1) & 3;

    fill(0, 0);
    fill(1, 1);

    auto compute = [&](int kt) {
        uint32_t sb = smb + (kt % 3) * GSTG;
        uint32_t baseA = sb + rowA * 64;
        uint32_t baseB = sb + 2 * GA_T + rowB * 64;
#pragma unroll
        for (int ks = 0; ks < 2; ks++) {
            const uint32_t cAo = (uint32_t)(((ks * 2 + lah) ^ keyA) << 4);
            const uint32_t cBo = (uint32_t)(((ks * 2 + lbkc) ^ keyB) << 4);
            uint32_t fah[2][4], fal[2][4];
#pragma unroll
            for (int mf = 0; mf < 2; mf++) {
                ldsm_x4(fah[mf], baseA + mf * 1024 + cAo);
                ldsm_x4(fal[mf], baseA + GA_T + mf * 1024 + cAo);
            }
#pragma unroll
            for (int np = 0; np < 4; np++) {
                uint32_t fbh[4], fbl[4];
                ldsm_x4(fbh, baseB + np * 1024 + cBo);
                ldsm_x4(fbl, baseB + GB_T + np * 1024 + cBo);
#pragma unroll
                for (int mf = 0; mf < 2; mf++) {
                    mma16816(acc[mf][2 * np],     fah[mf], fbh);
                    mma16816(acc[mf][2 * np],     fah[mf], fbl);
                    mma16816(acc[mf][2 * np],     fal[mf], fbh);
                    mma16816(acc[mf][2 * np + 1], fah[mf], fbh + 2);
                    mma16816(acc[mf][2 * np + 1], fah[mf], fbl + 2);
                    mma16816(acc[mf][2 * np + 1], fal[mf], fbh + 2);
                }
            }
        }
    };

    for (int kt = 0; kt < NK; kt++) {
        CP_WAIT(1);
        __syncthreads();
        compute(kt);
        if (kt + 2 < NK) fill((kt + 2) % 3, kt + 2);
        else CP_COMMIT();
    }

    // Epilogue
    const int r0 = brow * 128 + wm * 32 + (lane >> 2);
    const int c0 = bcol * 128 + wn * 64 + (lane & 3) * 2;
    if (C) {
#pragma unroll
        for (int mf = 0; mf < 2; mf++)
#pragma unroll
            for (int nf = 0; nf < 8; nf++) {
                int row = r0 + mf * 16, col = c0 + nf * 8;
                *(float2*)&C[(size_t)row * N + col] = make_float2(acc[mf][nf][0], acc[mf][nf][1]);
                *(float2*)&C[(size_t)(row + 8) * N + col] = make_float2(acc[mf][nf][2], acc[mf][nf][3]);
            }
    } else {
#pragma unroll
        for (int mf = 0; mf < 2; mf++)
#pragma unroll
            for (int nf = 0; nf < 8; nf++) {
                int row = r0 + mf * 16, col = c0 + nf * 8;
                float* a = acc[mf][nf];
                float h0 = truncbf(a[0]), h1 = truncbf(a[1]), h2 = truncbf(a[2]), h3 = truncbf(a[3]);
                *(uint32_t*)&Chi[(size_t)row * N + col] = packhi2(a[0], a[1]);
                *(uint32_t*)&Chi[(size_t)(row + 8) * N + col] = packhi2(a[2], a[3]);
                *(uint32_t*)&Clo[(size_t)row * N + col] = packbf2(a[0] - h0, a[1] - h1);
                *(uint32_t*)&Clo[(size_t)(row + 8) * N + col] = packbf2(a[2] - h2, a[3] - h3);
            }
    }
}

// ---------------------------------------------------------------------------
// fp16 single-term GEMM: C[M,N] = A[M,K] @ B[N,K]^T, fp32 accumulate/out.
// Same R13 skeleton: CTA 128x128, BK=32, 3-stage, fill-after-compute,
// 2 CTAs/SM, 8 warps 4x2 (warp tile 32x64). Stage = 16 KB.
// ---------------------------------------------------------------------------
#define FT_T   (128 * 64)                // 8192 bytes per operand tile
#define FSTG   (2 * FT_T)                // 16384
#define GEMMF_SMEM (3 * FSTG)            // 49152

__global__ void __launch_bounds__(256, 2) gemm_fp16_kernel(
    const __half* __restrict__ A, const __half* __restrict__ Bm,
    float* __restrict__ C, int M, int N, int K)
{
    extern __shared__ char smem[];
    const uint32_t smb = smem_to_u32(smem);
    const int tid = threadIdx.x;
    const int wid = tid >> 5, lane = tid & 31;
    const int brow = blockIdx.y, bcol = blockIdx.x;
    const int NK = K >> 5;

    auto fill = [&](int st, int kt) {
        uint32_t sb = smb + st * FSTG;
        const int kof = kt * 32;
#pragma unroll
        for (int t = 0; t < 2; t++) {
            int idx = tid + t * 256;
            int r = idx >> 2, c = idx & 3;
            uint32_t off = r * 64 + ((c ^ ((r >> 1) & 3)) << 4);
            cp16(sb + off, A + (size_t)(brow * 128 + r) * K + kof + c * 8);
            cp16(sb + FT_T + off, Bm + (size_t)(bcol * 128 + r) * K + kof + c * 8);
        }
        CP_COMMIT();
    };

    float acc[2][8][4];
#pragma unroll
    for (int mf = 0; mf < 2; mf++)
#pragma unroll
        for (int nf = 0; nf < 8; nf++)
#pragma unroll
            for (int e = 0; e < 4; e++) acc[mf][nf][e] = 0.f;

    const int wm = wid & 3, wn = wid >> 2;
    const int la = lane & 15, lah = lane >> 4;
    const int lbn2 = (lane & 7) + ((lane >> 4) << 3);
    const int lbkc = (lane >> 3) & 1;

    const int rowA = wm * 32 + la;
    const int keyA = (rowA >> 1) & 3;
    const int rowB = wn * 64 + lbn2;
    const int keyB = (rowB >> 1) & 3;

    fill(0, 0);
    fill(1, 1);

    auto compute = [&](int kt) {
        uint32_t sb = smb + (kt % 3) * FSTG;
        uint32_t baseA = sb + rowA * 64;
        uint32_t baseB = sb + FT_T + rowB * 64;
#pragma unroll
        for (int ks = 0; ks < 2; ks++) {
            const uint32_t cAo = (uint32_t)(((ks * 2 + lah) ^ keyA) << 4);
            const uint32_t cBo = (uint32_t)(((ks * 2 + lbkc) ^ keyB) << 4);
            uint32_t fa[2][4];
#pragma unroll
            for (int mf = 0; mf < 2; mf++)
                ldsm_x4(fa[mf], baseA + mf * 1024 + cAo);
#pragma unroll
            for (int np = 0; np < 4; np++) {
                uint32_t fb[4];
                ldsm_x4(fb, baseB + np * 1024 + cBo);
#pragma unroll
                for (int mf = 0; mf < 2; mf++) {
                    mma16816h(acc[mf][2 * np],     fa[mf], fb);
                    mma16816h(acc[mf][2 * np + 1], fa[mf], fb + 2);
                }
            }
        }
    };

    for (int kt = 0; kt < NK; kt++) {
        CP_WAIT(1);
        __syncthreads();
        compute(kt);
        if (kt + 2 < NK) fill((kt + 2) % 3, kt + 2);
        else CP_COMMIT();
    }

    const int r0 = brow * 128 + wm * 32 + (lane >> 2);
    const int c0 = bcol * 128 + wn * 64 + (lane & 3) * 2;
#pragma unroll
    for (int mf = 0; mf < 2; mf++)
#pragma unroll
        for (int nf = 0; nf < 8; nf++) {
            int row = r0 + mf * 16, col = c0 + nf * 8;
            *(float2*)&C[(size_t)row * N + col] = make_float2(acc[mf][nf][0], acc[mf][nf][1]);
            *(float2*)&C[(size_t)(row + 8) * N + col] = make_float2(acc[mf][nf][2], acc[mf][nf][3]);
        }
}

// ---------------------------------------------------------------------------
// Causal flash attention on tensor cores (bf16 hi/lo split precision).
// Same as R14 except the epilogue emits y as single fp16.
// ---------------------------------------------------------------------------
#define AROWB 272                        // 128 bf16 = 256B + 16B pad
#define KHI_O 0
#define KLO_O (64 * AROWB)               // 17408
#define VHI_O (2 * 64 * AROWB)
#define VLO_O (3 * 64 * AROWB)
#define STG_SZ (4 * 64 * AROWB)          // 69632
#define ATTN_SMEM (3 * STG_SZ)           // 208896

__global__ void __launch_bounds__(256, 1) attn_mma_kernel(
    const __nv_bfloat16* __restrict__ qhv, const __nv_bfloat16* __restrict__ qlv,
    __half* __restrict__ y16)
{
    extern __shared__ char smem[];
    const uint32_t smb = smem_to_u32(smem);
    const int tid = threadIdx.x, wid = tid >> 5, lane = tid & 31;
    const int qb = 15 - blockIdx.x;              // heavy CTAs first
    const int bh = blockIdx.y, b = bh >> 4, h = bh & 15;
    const int nkb = 2 * qb + 2;
    const size_t gbase = (size_t)b * S_ * QKV_LD + (size_t)h * HD;
    const float csc = 0.12752963413397017f;      // 1/sqrt(128) * log2(e)

    // ---- Prologue: stage Q in stage-2's smem, ldsm into registers ----
    const uint32_t qsb = smb + 2 * STG_SZ;
#pragma unroll
    for (int t = 0; t < 8; t++) {
        int idx = tid + t * 256;
        int r = idx >> 4, c = idx & 15;
        size_t g = gbase + (size_t)(qb * 128 + r) * QKV_LD + c * 8;
        cp16(qsb + r * AROWB + c * 16, qhv + g);
        cp16(qsb + 128 * AROWB + r * AROWB + c * 16, qlv + g);
    }
    CP_COMMIT();

    const int la = lane & 15, lah = lane >> 4;
    const int lbn2 = (lane & 7) + ((lane >> 4) << 3);
    const int lbk2 = ((lane >> 3) & 1) * 16;
    const int grow = qb * 128 + wid * 16 + (lane >> 2);

    CP_WAIT(0);
    __syncthreads();
    uint32_t Qh[8][4], Ql[8][4];
    {
        const uint32_t aQ = qsb + (wid * 16 + la) * AROWB + lah * 16;
#pragma unroll
        for (int ks = 0; ks < 8; ks++) {
            ldsm_x4(Qh[ks], aQ + ks * 32);
            ldsm_x4(Ql[ks], aQ + 128 * AROWB + ks * 32);
        }
    }
    __syncthreads();

    auto fillKV = [&](int kb) {
        uint32_t sb = smb + (kb % 3) * STG_SZ;
#pragma unroll
        for (int t = 0; t < 4; t++) {
            int idx = tid + t * 256;
            int r = idx >> 4, c = idx & 15;
            size_t g = gbase + (size_t)(kb * 64 + r) * QKV_LD + c * 8;
            cp16(sb + KHI_O + r * AROWB + c * 16, qhv + g + C_);
            cp16(sb + KLO_O + r * AROWB + c * 16, qlv + g + C_);
            cp16(sb + VHI_O + r * AROWB + c * 16, qhv + g + 2 * C_);
            cp16(sb + VLO_O + r * AROWB + c * 16, qlv + g + 2 * C_);
        }
        CP_COMMIT();
    };
    fillKV(0);
    fillKV(1);

    float O[16][4];
#pragma unroll
    for (int nf = 0; nf < 16; nf++)
#pragma unroll
        for (int e = 0; e < 4; e++) O[nf][e] = 0.f;
    float m0 = -1e30f, m1 = -1e30f, l0 = 0.f, l1 = 0.f;

    for (int kb = 0; kb < nkb; kb++) {
        CP_WAIT(1);
        __syncthreads();
        const uint32_t kvb = smb + (kb % 3) * STG_SZ;
        const uint32_t aKh = kvb + KHI_O + lbn2 * AROWB + lbk2;
        const uint32_t aKl = kvb + KLO_O + lbn2 * AROWB + lbk2;

        float S[8][4];
#pragma unroll
        for (int nf = 0; nf < 8; nf++)
#pragma unroll
            for (int e = 0; e < 4; e++) S[nf][e] = 0.f;

#pragma unroll
        for (int ks = 0; ks < 8; ks++) {
#pragma unroll
            for (int np = 0; np < 4; np++) {
                uint32_t fkh[4], fkl[4];
                ldsm_x4(fkh, aKh + np * 16 * AROWB + ks * 32);
                ldsm_x4(fkl, aKl + np * 16 * AROWB + ks * 32);
                mma16816(S[2 * np],     Qh[ks], fkh);
                mma16816(S[2 * np],     Qh[ks], fkl);
                mma16816(S[2 * np],     Ql[ks], fkh);
                mma16816(S[2 * np + 1], Qh[ks], fkh + 2);
                mma16816(S[2 * np + 1], Qh[ks], fkl + 2);
                mma16816(S[2 * np + 1], Ql[ks], fkh + 2);
            }
        }

        const bool diag = (kb >= 2 * qb);
#pragma unroll
        for (int nf = 0; nf < 8; nf++)
#pragma unroll
            for (int e = 0; e < 4; e++) {
                float v = S[nf][e] * csc;
                if (diag) {
                    int col = kb * 64 + nf * 8 + (lane & 3) * 2 + (e & 1);
                    int row = grow + ((e & 2) ? 8 : 0);
                    if (col > row) v = -1e30f;
                }
                S[nf][e] = v;
            }

        float t0 = -1e30f, t1 = -1e30f;
#pragma unroll
        for (int nf = 0; nf < 8; nf++) {
            t0 = fmaxf(t0, fmaxf(S[nf][0], S[nf][1]));
            t1 = fmaxf(t1, fmaxf(S[nf][2], S[nf][3]));
        }
        t0 = fmaxf(t0, __shfl_xor_sync(0xffffffffu, t0, 1));
        t0 = fmaxf(t0, __shfl_xor_sync(0xffffffffu, t0, 2));
        t1 = fmaxf(t1, __shfl_xor_sync(0xffffffffu, t1, 1));
        t1 = fmaxf(t1, __shfl_xor_sync(0xffffffffu, t1, 2));
        float mn0 = fmaxf(m0, t0), mn1 = fmaxf(m1, t1);
        float a0 = ex2f(m0 - mn0), a1 = ex2f(m1 - mn1);
        m0 = mn0; m1 = mn1;
        float rs0 = 0.f, rs1 = 0.f;
#pragma unroll
        for (int nf = 0; nf < 8; nf++) {
            S[nf][0] = ex2f(S[nf][0] - mn0);
            S[nf][1] = ex2f(S[nf][1] - mn0);
            S[nf][2] = ex2f(S[nf][2] - mn1);
            S[nf][3] = ex2f(S[nf][3] - mn1);
            rs0 += S[nf][0] + S[nf][1];
            rs1 += S[nf][2] + S[nf][3];
        }
        l0 = l0 * a0 + rs0;
        l1 = l1 * a1 + rs1;
#pragma unroll
        for (int nf = 0; nf < 16; nf++) {
            O[nf][0] *= a0; O[nf][1] *= a0; O[nf][2] *= a1; O[nf][3] *= a1;
        }

#pragma unroll
        for (int kk = 0; kk < 4; kk++) {
            float* s0 = S[2 * kk];
            float* s1 = S[2 * kk + 1];
            uint32_t ph[4], pl[4];
            ph[0] = packhi2(s0[0], s0[1]);
            ph[1] = packhi2(s0[2], s0[3]);
            ph[2] = packhi2(s1[0], s1[1]);
            ph[3] = packhi2(s1[2], s1[3]);
            pl[0] = packbf2(s0[0] - truncbf(s0[0]), s0[1] - truncbf(s0[1]));
            pl[1] = packbf2(s0[2] - truncbf(s0[2]), s0[3] - truncbf(s0[3]));
            pl[2] = packbf2(s1[0] - truncbf(s1[0]), s1[1] - truncbf(s1[1]));
            pl[3] = packbf2(s1[2] - truncbf(s1[2]), s1[3] - truncbf(s1[3]));
#pragma unroll
            for (int n2 = 0; n2 < 8; n2++) {
                uint32_t fvh[4], fvl[4];
                ldsm_x4_t(fvh, kvb + VHI_O + (kk * 16 + la) * AROWB + n2 * 32 + lah * 16);
                ldsm_x4_t(fvl, kvb + VLO_O + (kk * 16 + la) * AROWB + n2 * 32 + lah * 16);
                mma16816(O[2 * n2],     ph, fvh);
                mma16816(O[2 * n2],     ph, fvl);
                mma16816(O[2 * n2],     pl, fvh);
                mma16816(O[2 * n2 + 1], ph, fvh + 2);
                mma16816(O[2 * n2 + 1], ph, fvl + 2);
                mma16816(O[2 * n2 + 1], pl, fvh + 2);
            }
        }

        if (kb + 2 < nkb) fillKV(kb + 2);
    }

    // ---- epilogue: O/l -> single fp16 y ----
    l0 += __shfl_xor_sync(0xffffffffu, l0, 1);
    l0 += __shfl_xor_sync(0xffffffffu, l0, 2);
    l1 += __shfl_xor_sync(0xffffffffu, l1, 1);
    l1 += __shfl_xor_sync(0xffffffffu, l1, 2);
    const float i0 = 1.f / l0, i1 = 1.f / l1;
    const size_t o0 = ((size_t)b * S_ + grow) * C_ + h * HD + (lane & 3) * 2;
    const size_t o1 = o0 + 8 * C_;
#pragma unroll
    for (int nf = 0; nf < 16; nf++) {
        *(uint32_t*)(y16 + o0 + nf * 8) = packf16x2(O[nf][0] * i0, O[nf][1] * i0);
        *(uint32_t*)(y16 + o1 + nf * 8) = packf16x2(O[nf][2] * i1, O[nf][3] * i1);
    }
}

// ---------------------------------------------------------------------------
extern "C" void kernel_launch(void* const* d_in, const int* in_sizes, int n_in,
                              void* d_out, int out_size) {
    const float* x  = (const float*)d_in[0];
    const float* Wa = (const float*)d_in[1];
    const float* Wp = (const float*)d_in[2];
    float* out = (float*)d_out;

    __nv_bfloat16 *qkvhi, *qkvlo, *xhi, *xlo, *wahi, *walo;
    __half *y16, *wp16;
    cudaGetSymbolAddress((void**)&qkvhi, g_qkvhi);
    cudaGetSymbolAddress((void**)&qkvlo, g_qkvlo);
    cudaGetSymbolAddress((void**)&xhi, g_xhi);
    cudaGetSymbolAddress((void**)&xlo, g_xlo);
    cudaGetSymbolAddress((void**)&y16, g_y16);
    cudaGetSymbolAddress((void**)&wahi, g_wahi);
    cudaGetSymbolAddress((void**)&walo, g_walo);
    cudaGetSymbolAddress((void**)&wp16, g_wp16);

    cudaFuncSetAttribute(gemm_hmma_kernel, cudaFuncAttributeMaxDynamicSharedMemorySize, GEMM_SMEM);
    cudaFuncSetAttribute(gemm_fp16_kernel, cudaFuncAttributeMaxDynamicSharedMemorySize, GEMMF_SMEM);
    cudaFuncSetAttribute(attn_mma_kernel, cudaFuncAttributeMaxDynamicSharedMemorySize, ATTN_SMEM);

    // 0) split/transpose operands
    int n4 = (MTOT * C_) / 4;
    split_kernel<<<(n4 + 255) / 256, 256>>>(x, xhi, xlo, n4);
    dim3 bT(32, 8);
    tsplit_kernel<<<dim3(QKV_LD / 32, C_ / 32), bT>>>(Wa, wahi, walo, C_, QKV_LD);
    tcvt16_kernel<<<dim3(C_ / 32, C_ / 32), bT>>>(Wp, wp16, C_, C_);

    // 1) QKV projection (bf16 3-term) -> bf16 hi/lo
    gemm_hmma_kernel<<<dim3(QKV_LD / 128, MTOT / 128), 256, GEMM_SMEM>>>(
        xhi, xlo, wahi, walo, nullptr, qkvhi, qkvlo, MTOT, QKV_LD, C_);

    // 2) Causal flash attention (bf16 3-term) -> fp16 y
    attn_mma_kernel<<<dim3(16, B_ * NH), 256, ATTN_SMEM>>>(qkvhi, qkvlo, y16);

    // 3) Output projection (fp16 single-term) -> fp32 out
    gemm_fp16_kernel<<<dim3(C_ / 128, MTOT / 128), 256, GEMMF_SMEM>>>(
        y16, wp16, out, MTOT, C_, C_);
}

// round 16
// speedup vs baseline: 3.5518x; 2.1505x over previous
#include <cuda_runtime.h>
#include <cuda_bf16.h>
#include <cuda_fp16.h>
#include <cstdint>
#include <math.h>

// Problem constants
#define B_   4
#define S_   2048
#define C_   2048
#define NH   16
#define HD   128
#define QKV_LD 6144
#define MTOT (B_ * S_)          // 8192

// ---------------------------------------------------------------------------
// Scratch (__device__ globals — allocation-free rule)
// ---------------------------------------------------------------------------
__device__ __half g_qkv16[(size_t)MTOT * QKV_LD];
__device__ __half g_x16[(size_t)MTOT * C_];
__device__ __half g_y16[(size_t)MTOT * C_];
__device__ __half g_wa16[(size_t)QKV_LD * C_];    // W_attn^T [6144,2048]
__device__ __half g_wp16[(size_t)C_ * C_];        // W_proj^T [2048,2048]

// ---------------------------------------------------------------------------
// PTX helpers (base compute_103 ISA: cp.async / ldmatrix / mma.sync)
// ---------------------------------------------------------------------------
__device__ __forceinline__ uint32_t smem_to_u32(const void* p) {
    uint32_t a;
    asm("{ .reg .u64 t; cvta.to.shared.u64 t, %1; cvt.u32.u64 %0, t; }" : "=r"(a) : "l"(p));
    return a;
}
__device__ __forceinline__ void cp16(uint32_t dst, const void* src) {
    asm volatile("cp.async.cg.shared.global [%0], [%1], 16;" :: "r"(dst), "l"(src));
}
#define CP_COMMIT() asm volatile("cp.async.commit_group;" ::: "memory")
#define CP_WAIT(n)  asm volatile("cp.async.wait_group %0;" :: "n"(n) : "memory")

__device__ __forceinline__ void ldsm_x4(uint32_t r[4], uint32_t addr) {
    asm volatile("ldmatrix.sync.aligned.m8n8.x4.shared.b16 {%0,%1,%2,%3}, [%4];"
        : "=r"(r[0]), "=r"(r[1]), "=r"(r[2]), "=r"(r[3]) : "r"(addr));
}
__device__ __forceinline__ void ldsm_x4_t(uint32_t r[4], uint32_t addr) {
    asm volatile("ldmatrix.sync.aligned.m8n8.x4.trans.shared.b16 {%0,%1,%2,%3}, [%4];"
        : "=r"(r[0]), "=r"(r[1]), "=r"(r[2]), "=r"(r[3]) : "r"(addr));
}
__device__ __forceinline__ void mma16816h(float d[4], const uint32_t a[4], const uint32_t b[2]) {
    asm volatile(
        "mma.sync.aligned.m16n8k16.row.col.f32.f16.f16.f32 "
        "{%0,%1,%2,%3}, {%4,%5,%6,%7}, {%8,%9}, {%0,%1,%2,%3};"
        : "+f"(d[0]), "+f"(d[1]), "+f"(d[2]), "+f"(d[3])
        : "r"(a[0]), "r"(a[1]), "r"(a[2]), "r"(a[3]), "r"(b[0]), "r"(b[1]));
}
__device__ __forceinline__ float ex2f(float x) {
    float y; asm("ex2.approx.f32 %0, %1;" : "=f"(y) : "f"(x)); return y;
}
__device__ __forceinline__ uint32_t packf16x2(float lo, float hi) {
    uint32_t r;
    asm("cvt.rn.f16x2.f32 %0, %1, %2;" : "=r"(r) : "f"(hi), "f"(lo));
    return r;
}

// ---------------------------------------------------------------------------
// fp32 -> fp16 convert (flat)
// ---------------------------------------------------------------------------
__global__ void cvt16_kernel(const float* __restrict__ in,
                             __half* __restrict__ out, int n4) {
    int i = blockIdx.x * blockDim.x + threadIdx.x;
    if (i >= n4) return;
    float4 v = ((const float4*)in)[i];
    uint2 o;
    o.x = packf16x2(v.x, v.y);
    o.y = packf16x2(v.z, v.w);
    ((uint2*)out)[i] = o;
}

// Transpose + convert: in[K,N] fp32 -> fp16 [N,K]
__global__ void tcvt16_kernel(const float* __restrict__ in,
                              __half* __restrict__ out, int K, int N) {
    __shared__ float t[32][33];
    int n0 = blockIdx.x * 32, k0 = blockIdx.y * 32;
    int tx = threadIdx.x, ty = threadIdx.y;
    for (int i = ty; i < 32; i += 8)
        t[i][tx] = in[(size_t)(k0 + i) * N + n0 + tx];
    __syncthreads();
    for (int i = ty; i < 32; i += 8)
        out[(size_t)(n0 + i) * K + k0 + tx] = __float2half(t[tx][i]);
}

// ---------------------------------------------------------------------------
// fp16 single-term GEMM: C[M,N] = A[M,K] @ B[N,K]^T, fp32 accumulate.
// Output to fp32 C or fp16 C16 (one is null).
// R13 skeleton: CTA 128x128, BK=32, 3-stage XOR-swizzled smem,
// fill-after-compute, 256 threads = 8 warps 4x2 (warp tile 32x64), 2 CTAs/SM.
// Swizzle: 16B chunk c of row r stored at r*64 + ((c ^ ((r>>1)&3))*16).
// ---------------------------------------------------------------------------
#define FT_T   (128 * 64)                // 8192 bytes per operand tile
#define FSTG   (2 * FT_T)                // 16384
#define GEMMF_SMEM (3 * FSTG)            // 49152

__global__ void __launch_bounds__(256, 2) gemm_fp16_kernel(
    const __half* __restrict__ A, const __half* __restrict__ Bm,
    float* __restrict__ C, __half* __restrict__ C16,
    int M, int N, int K)
{
    extern __shared__ char smem[];
    const uint32_t smb = smem_to_u32(smem);
    const int tid = threadIdx.x;
    const int wid = tid >> 5, lane = tid & 31;
    const int brow = blockIdx.y, bcol = blockIdx.x;
    const int NK = K >> 5;

    auto fill = [&](int st, int kt) {
        uint32_t sb = smb + st * FSTG;
        const int kof = kt * 32;
#pragma unroll
        for (int t = 0; t < 2; t++) {
            int idx = tid + t * 256;
            int r = idx >> 2, c = idx & 3;
            uint32_t off = r * 64 + ((c ^ ((r >> 1) & 3)) << 4);
            cp16(sb + off, A + (size_t)(brow * 128 + r) * K + kof + c * 8);
            cp16(sb + FT_T + off, Bm + (size_t)(bcol * 128 + r) * K + kof + c * 8);
        }
        CP_COMMIT();
    };

    float acc[2][8][4];
#pragma unroll
    for (int mf = 0; mf < 2; mf++)
#pragma unroll
        for (int nf = 0; nf < 8; nf++)
#pragma unroll
            for (int e = 0; e < 4; e++) acc[mf][nf][e] = 0.f;

    const int wm = wid & 3, wn = wid >> 2;
    const int la = lane & 15, lah = lane >> 4;
    const int lbn2 = (lane & 7) + ((lane >> 4) << 3);
    const int lbkc = (lane >> 3) & 1;

    const int rowA = wm * 32 + la;
    const int keyA = (rowA >> 1) & 3;
    const int rowB = wn * 64 + lbn2;
    const int keyB = (rowB >> 1) & 3;

    fill(0, 0);
    fill(1, 1);

    auto compute = [&](int kt) {
        uint32_t sb = smb + (kt % 3) * FSTG;
        uint32_t baseA = sb + rowA * 64;
        uint32_t baseB = sb + FT_T + rowB * 64;
#pragma unroll
        for (int ks = 0; ks < 2; ks++) {
            const uint32_t cAo = (uint32_t)(((ks * 2 + lah) ^ keyA) << 4);
            const uint32_t cBo = (uint32_t)(((ks * 2 + lbkc) ^ keyB) << 4);
            uint32_t fa[2][4];
#pragma unroll
            for (int mf = 0; mf < 2; mf++)
                ldsm_x4(fa[mf], baseA + mf * 1024 + cAo);
#pragma unroll
            for (int np = 0; np < 4; np++) {
                uint32_t fb[4];
                ldsm_x4(fb, baseB + np * 1024 + cBo);
#pragma unroll
                for (int mf = 0; mf < 2; mf++) {
                    mma16816h(acc[mf][2 * np],     fa[mf], fb);
                    mma16816h(acc[mf][2 * np + 1], fa[mf], fb + 2);
                }
            }
        }
    };

    for (int kt = 0; kt < NK; kt++) {
        CP_WAIT(1);
        __syncthreads();
        compute(kt);
        if (kt + 2 < NK) fill((kt + 2) % 3, kt + 2);
        else CP_COMMIT();
    }

    const int r0 = brow * 128 + wm * 32 + (lane >> 2);
    const int c0 = bcol * 128 + wn * 64 + (lane & 3) * 2;
    if (C) {
#pragma unroll
        for (int mf = 0; mf < 2; mf++)
#pragma unroll
            for (int nf = 0; nf < 8; nf++) {
                int row = r0 + mf * 16, col = c0 + nf * 8;
                *(float2*)&C[(size_t)row * N + col] = make_float2(acc[mf][nf][0], acc[mf][nf][1]);
                *(float2*)&C[(size_t)(row + 8) * N + col] = make_float2(acc[mf][nf][2], acc[mf][nf][3]);
            }
    } else {
#pragma unroll
        for (int mf = 0; mf < 2; mf++)
#pragma unroll
            for (int nf = 0; nf < 8; nf++) {
                int row = r0 + mf * 16, col = c0 + nf * 8;
                float* a = acc[mf][nf];
                *(uint32_t*)&C16[(size_t)row * N + col] = packf16x2(a[0], a[1]);
                *(uint32_t*)&C16[(size_t)(row + 8) * N + col] = packf16x2(a[2], a[3]);
            }
    }
}

// ---------------------------------------------------------------------------
// Causal flash attention, single-term fp16 (fp32 accumulate).
// CTA = 128 q rows of one (b,h); 8 warps, each warp 16 full rows.
// Q fragments in registers; 3-stage KV pipeline, one barrier per kv-block,
// fillKV after the PV loop.
// ---------------------------------------------------------------------------
#define AROWB 272                        // 128 fp16 = 256B + 16B pad
#define KS_O  0
#define VS_O  (64 * AROWB)               // 17408
#define STG_SZ (2 * 64 * AROWB)          // 34816
#define ATTN_SMEM (3 * STG_SZ)           // 104448

__global__ void __launch_bounds__(256, 1) attn_mma_kernel(
    const __half* __restrict__ qkv, __half* __restrict__ y16)
{
    extern __shared__ char smem[];
    const uint32_t smb = smem_to_u32(smem);
    const int tid = threadIdx.x, wid = tid >> 5, lane = tid & 31;
    const int qb = 15 - blockIdx.x;              // heavy CTAs first
    const int bh = blockIdx.y, b = bh >> 4, h = bh & 15;
    const int nkb = 2 * qb + 2;
    const size_t gbase = (size_t)b * S_ * QKV_LD + (size_t)h * HD;
    const float csc = 0.12752963413397017f;      // 1/sqrt(128) * log2(e)

    // ---- Prologue: stage Q (128 rows) in stage-2's smem, ldsm to regs ----
    const uint32_t qsb = smb + 2 * STG_SZ;
#pragma unroll
    for (int t = 0; t < 8; t++) {
        int idx = tid + t * 256;                 // 0..2047
        int r = idx >> 4, c = idx & 15;
        cp16(qsb + r * AROWB + c * 16,
             qkv + gbase + (size_t)(qb * 128 + r) * QKV_LD + c * 8);
    }
    CP_COMMIT();

    const int la = lane & 15, lah = lane >> 4;
    const int lbn2 = (lane & 7) + ((lane >> 4) << 3);
    const int lbk2 = ((lane >> 3) & 1) * 16;
    const int grow = qb * 128 + wid * 16 + (lane >> 2);

    CP_WAIT(0);
    __syncthreads();
    uint32_t Qf[8][4];
    {
        const uint32_t aQ = qsb + (wid * 16 + la) * AROWB + lah * 16;
#pragma unroll
        for (int ks = 0; ks < 8; ks++)
            ldsm_x4(Qf[ks], aQ + ks * 32);
    }
    __syncthreads();   // all reads of Q smem done before stage 2 is recycled

    auto fillKV = [&](int kb) {
        uint32_t sb = smb + (kb % 3) * STG_SZ;
#pragma unroll
        for (int t = 0; t < 4; t++) {
            int idx = tid + t * 256;             // 0..1023
            int r = idx >> 4, c = idx & 15;
            size_t g = gbase + (size_t)(kb * 64 + r) * QKV_LD + c * 8;
            cp16(sb + KS_O + r * AROWB + c * 16, qkv + g + C_);
            cp16(sb + VS_O + r * AROWB + c * 16, qkv + g + 2 * C_);
        }
        CP_COMMIT();
    };
    fillKV(0);
    fillKV(1);

    float O[16][4];
#pragma unroll
    for (int nf = 0; nf < 16; nf++)
#pragma unroll
        for (int e = 0; e < 4; e++) O[nf][e] = 0.f;
    float m0 = -1e30f, m1 = -1e30f, l0 = 0.f, l1 = 0.f;

    for (int kb = 0; kb < nkb; kb++) {
        CP_WAIT(1);
        __syncthreads();             // stage kb visible; stage (kb+2)%3 free
        const uint32_t kvb = smb + (kb % 3) * STG_SZ;
        const uint32_t aK = kvb + KS_O + lbn2 * AROWB + lbk2;

        // ---- S = Q K^T ----
        float S[8][4];
#pragma unroll
        for (int nf = 0; nf < 8; nf++)
#pragma unroll
            for (int e = 0; e < 4; e++) S[nf][e] = 0.f;

#pragma unroll
        for (int ks = 0; ks < 8; ks++) {
#pragma unroll
            for (int np = 0; np < 4; np++) {
                uint32_t fk[4];
                ldsm_x4(fk, aK + np * 16 * AROWB + ks * 32);
                mma16816h(S[2 * np],     Qf[ks], fk);
                mma16816h(S[2 * np + 1], Qf[ks], fk + 2);
            }
        }

        // ---- scale + causal mask ----
        const bool diag = (kb >= 2 * qb);
#pragma unroll
        for (int nf = 0; nf < 8; nf++)
#pragma unroll
            for (int e = 0; e < 4; e++) {
                float v = S[nf][e] * csc;
                if (diag) {
                    int col = kb * 64 + nf * 8 + (lane & 3) * 2 + (e & 1);
                    int row = grow + ((e & 2) ? 8 : 0);
                    if (col > row) v = -1e30f;
                }
                S[nf][e] = v;
            }

        // ---- online softmax ----
        float t0 = -1e30f, t1 = -1e30f;
#pragma unroll
        for (int nf = 0; nf < 8; nf++) {
            t0 = fmaxf(t0, fmaxf(S[nf][0], S[nf][1]));
            t1 = fmaxf(t1, fmaxf(S[nf][2], S[nf][3]));
        }
        t0 = fmaxf(t0, __shfl_xor_sync(0xffffffffu, t0, 1));
        t0 = fmaxf(t0, __shfl_xor_sync(0xffffffffu, t0, 2));
        t1 = fmaxf(t1, __shfl_xor_sync(0xffffffffu, t1, 1));
        t1 = fmaxf(t1, __shfl_xor_sync(0xffffffffu, t1, 2));
        float mn0 = fmaxf(m0, t0), mn1 = fmaxf(m1, t1);
        float a0 = ex2f(m0 - mn0), a1 = ex2f(m1 - mn1);
        m0 = mn0; m1 = mn1;
        float rs0 = 0.f, rs1 = 0.f;
#pragma unroll
        for (int nf = 0; nf < 8; nf++) {
            S[nf][0] = ex2f(S[nf][0] - mn0);
            S[nf][1] = ex2f(S[nf][1] - mn0);
            S[nf][2] = ex2f(S[nf][2] - mn1);
            S[nf][3] = ex2f(S[nf][3] - mn1);
            rs0 += S[nf][0] + S[nf][1];
            rs1 += S[nf][2] + S[nf][3];
        }
        l0 = l0 * a0 + rs0;
        l1 = l1 * a1 + rs1;
#pragma unroll
        for (int nf = 0; nf < 16; nf++) {
            O[nf][0] *= a0; O[nf][1] *= a0; O[nf][2] *= a1; O[nf][3] *= a1;
        }

        // ---- O += P V (P packed to fp16 in registers) ----
#pragma unroll
        for (int kk = 0; kk < 4; kk++) {
            float* s0 = S[2 * kk];
            float* s1 = S[2 * kk + 1];
            uint32_t ph[4];
            ph[0] = packf16x2(s0[0], s0[1]);
            ph[1] = packf16x2(s0[2], s0[3]);
            ph[2] = packf16x2(s1[0], s1[1]);
            ph[3] = packf16x2(s1[2], s1[3]);
#pragma unroll
            for (int n2 = 0; n2 < 8; n2++) {
                uint32_t fv[4];
                ldsm_x4_t(fv, kvb + VS_O + (kk * 16 + la) * AROWB + n2 * 32 + lah * 16);
                mma16816h(O[2 * n2],     ph, fv);
                mma16816h(O[2 * n2 + 1], ph, fv + 2);
            }
        }

        if (kb + 2 < nkb) fillKV(kb + 2);   // overlaps MMA drain
    }

    // ---- epilogue: O/l -> fp16 y ----
    l0 += __shfl_xor_sync(0xffffffffu, l0, 1);
    l0 += __shfl_xor_sync(0xffffffffu, l0, 2);
    l1 += __shfl_xor_sync(0xffffffffu, l1, 1);
    l1 += __shfl_xor_sync(0xffffffffu, l1, 2);
    const float i0 = 1.f / l0, i1 = 1.f / l1;
    const size_t o0 = ((size_t)b * S_ + grow) * C_ + h * HD + (lane & 3) * 2;
    const size_t o1 = o0 + 8 * C_;
#pragma unroll
    for (int nf = 0; nf < 16; nf++) {
        *(uint32_t*)(y16 + o0 + nf * 8) = packf16x2(O[nf][0] * i0, O[nf][1] * i0);
        *(uint32_t*)(y16 + o1 + nf * 8) = packf16x2(O[nf][2] * i1, O[nf][3] * i1);
    }
}

// ---------------------------------------------------------------------------
extern "C" void kernel_launch(void* const* d_in, const int* in_sizes, int n_in,
                              void* d_out, int out_size) {
    const float* x  = (const float*)d_in[0];
    const float* Wa = (const float*)d_in[1];
    const float* Wp = (const float*)d_in[2];
    float* out = (float*)d_out;

    __half *qkv16, *x16, *y16, *wa16, *wp16;
    cudaGetSymbolAddress((void**)&qkv16, g_qkv16);
    cudaGetSymbolAddress((void**)&x16, g_x16);
    cudaGetSymbolAddress((void**)&y16, g_y16);
    cudaGetSymbolAddress((void**)&wa16, g_wa16);
    cudaGetSymbolAddress((void**)&wp16, g_wp16);

    cudaFuncSetAttribute(gemm_fp16_kernel, cudaFuncAttributeMaxDynamicSharedMemorySize, GEMMF_SMEM);
    cudaFuncSetAttribute(attn_mma_kernel, cudaFuncAttributeMaxDynamicSharedMemorySize, ATTN_SMEM);

    // 0) convert operands to fp16
    int n4 = (MTOT * C_) / 4;
    cvt16_kernel<<<(n4 + 255) / 256, 256>>>(x, x16, n4);
    dim3 bT(32, 8);
    tcvt16_kernel<<<dim3(QKV_LD / 32, C_ / 32), bT>>>(Wa, wa16, C_, QKV_LD);
    tcvt16_kernel<<<dim3(C_ / 32, C_ / 32), bT>>>(Wp, wp16, C_, C_);

    // 1) QKV projection (fp16) -> fp16 qkv
    gemm_fp16_kernel<<<dim3(QKV_LD / 128, MTOT / 128), 256, GEMMF_SMEM>>>(
        x16, wa16, nullptr, qkv16, MTOT, QKV_LD, C_);

    // 2) Causal flash attention (fp16) -> fp16 y
    attn_mma_kernel<<<dim3(16, B_ * NH), 256, ATTN_SMEM>>>(qkv16, y16);

    // 3) Output projection (fp16) -> fp32 out
    gemm_fp16_kernel<<<dim3(C_ / 128, MTOT / 128), 256, GEMMF_SMEM>>>(
        y16, wp16, out, nullptr, MTOT, C_, C_);
}